// round 11
// baseline (speedup 1.0000x reference)
#include <cuda_runtime.h>
#include <cuda_fp16.h>
#include <math.h>
#include <stdint.h>

#define NB   8
#define C1   256
#define C2   256
#define CM   128
#define HH   56
#define WW   56
#define HW   3136
#define NPIX (NB*HW)
#define GG   4
#define GC   32
#define EPSS 1e-5f
#define NOM  108
#define NCH2 72          // 72 K-chunks of 32
#define NSTG 4
#define XPW  66
#define STG4 16384

// scratch (device globals: allocation-free rule)
__device__ float g_h [NPIX*CM];
__device__ __half g_v [NPIX*CM];          // value proj now fp16
__device__ float g_om[NPIX*NOM];
__device__ __half g_xp_hi[8*58*XPW*256];
__device__ __half g_xp_lo[8*58*XPW*256];
__device__ __half g_wb_hi[36*128*64];
// fp16 hi/lo A-operands for the K=128 GEMMs
__device__ __half g_hb_hi[NPIX*CM], g_hb_lo[NPIX*CM];
__device__ __half g_tb_hi[NPIX*CM], g_tb_lo[NPIX*CM];
__device__ __half g_ob_hi[NPIX*CM], g_ob_lo[NPIX*CM];
// B operands (hi only), layout [kc(2)][n][64 k], k-major rows
__device__ __half g_wv_hi [2*128*64];
__device__ __half g_wom_hi[2*128*64];
__device__ __half g_wo_hi [2*256*64];

__device__ __forceinline__ float siluf(float v){ return v / (1.f + expf(-v)); }
__device__ __forceinline__ void split_h(float v, __half& hi, __half& lo) {
    hi = __float2half(v);
    lo = __float2half(v - __half2float(hi));
}

__device__ __forceinline__ uint32_t smem_to_u32(const void* p) {
    uint32_t a;
    asm("{ .reg .u64 t; cvta.to.shared.u64 t, %1; cvt.u32.u64 %0, t; }" : "=r"(a) : "l"(p));
    return a;
}
#define SWZ128(o) ((o) ^ (((o) >> 3) & 0x70))
#define SWZ64(o)  ((o) ^ (((o) >> 3) & 0x30))
#define CP_ASYNC16(sa, gp) \
    asm volatile("cp.async.cg.shared.global [%0], [%1], 16;" \
        :: "r"((uint32_t)(sa)), "l"(gp) : "memory")

__device__ __forceinline__ void ldsm4(uint32_t* r, uint32_t addr) {
    asm volatile("ldmatrix.sync.aligned.m8n8.x4.shared.b16 {%0,%1,%2,%3}, [%4];"
        : "=r"(r[0]), "=r"(r[1]), "=r"(r[2]), "=r"(r[3]) : "r"(addr));
}
__device__ __forceinline__ void mma16816(float* d, const uint32_t* a, uint32_t b0, uint32_t b1) {
    asm volatile("mma.sync.aligned.m16n8k16.row.col.f32.f16.f16.f32 "
        "{%0,%1,%2,%3}, {%4,%5,%6,%7}, {%8,%9}, {%0,%1,%2,%3};"
        : "+f"(d[0]), "+f"(d[1]), "+f"(d[2]), "+f"(d[3])
        : "r"(a[0]), "r"(a[1]), "r"(a[2]), "r"(a[3]), "r"(b0), "r"(b1));
}

// ===================== prep: pad/transpose/split x =====================
__global__ __launch_bounds__(256) void xprep(const float* __restrict__ x)
{
    const int b = blockIdx.x, img = b / 58, yp = b % 58;
    const size_t rowbase = ((size_t)img*58 + yp) * (XPW*256);
    const int t = threadIdx.x;
    uint2 z2 = make_uint2(0u, 0u);
    for (int i = t; i < XPW*256/4; i += 256) {
        ((uint2*)(g_xp_hi + rowbase))[i] = z2;
        ((uint2*)(g_xp_lo + rowbase))[i] = z2;
    }
    if (yp == 0 || yp == 57) return;
    __syncthreads();
    const int oy = yp - 1;
    __shared__ float sm[128*57];
    for (int pass = 0; pass < 2; pass++) {
        for (int i = t; i < 128*56; i += 256) {
            int c = i / 56, ox = i % 56;
            sm[c*57 + ox] = x[((size_t)(img*256 + pass*128 + c))*HW + oy*WW + ox];
        }
        __syncthreads();
        for (int i = t; i < 56*128; i += 256) {
            int ox = i >> 7, c = i & 127;
            float v = sm[c*57 + ox];
            size_t a = rowbase + (size_t)(ox+1)*256 + pass*128 + c;
            split_h(v, g_xp_hi[a], g_xp_lo[a]);
        }
        __syncthreads();
    }
}

// conv weights (hi only): w[o][c*9+tap] -> [chunk64=tap*4+cc][o][ci]
__global__ __launch_bounds__(256) void wprep(const float* __restrict__ w)
{
    int idx = blockIdx.x*256 + threadIdx.x;
    if (idx >= 36*128*64) return;
    int ci = idx & 63, o = (idx >> 6) & 127, ch = idx >> 13;
    int tap = ch >> 2, cc = ch & 3;
    g_wb_hi[idx] = __float2half(w[(size_t)o*2304 + (cc*64 + ci)*9 + tap]);
}

// fused GEMM-weight splits (hi only): wv (128), wom (72|36), wo (256)
__global__ __launch_bounds__(256) void prep_all(
    const float* __restrict__ winp, const float* __restrict__ woff,
    const float* __restrict__ wmsk, const float* __restrict__ wout)
{
    int idx = blockIdx.x*256 + threadIdx.x;   // 0 .. 65535
    const float* w1; const float* w2; int n1, n2, Ntot, li;
    __half* dhi;
    if (idx < 16384)      { li = idx;        w1 = winp; w2 = nullptr; n1 = 128; n2 = 0;  Ntot = 128; dhi = g_wv_hi;  }
    else if (idx < 32768) { li = idx-16384;  w1 = woff; w2 = wmsk;    n1 = 72;  n2 = 36; Ntot = 128; dhi = g_wom_hi; }
    else                  { li = idx-32768;  w1 = wout; w2 = nullptr; n1 = 256; n2 = 0;  Ntot = 256; dhi = g_wo_hi;  }
    int ki = li & 63;
    int n  = (li >> 6) % Ntot;
    int kc = li / (64*Ntot);
    int k  = kc*64 + ki;
    float v = 0.f;
    if (n < n1)           v = w1[(size_t)k*n1 + n];
    else if (n < n1 + n2) v = w2[(size_t)k*n2 + (n - n1)];
    dhi[li] = __float2half(v);
}

// ===================== conv1 via mma.sync fp16 hi/lo 2-term =====================
// CTA = (img, 1 output row): M=64, N=128, K = 72 chunks of 32.
// Stage 16KB (A hi/lo 4+4KB, B hi 8KB, 64B rows SW64), NSTG=4 -> 3 CTAs/SM.
// Loader uses rolling incremental pointers: ~8 ALU ops/chunk.
__global__ __launch_bounds__(256, 3) void conv1_mma(
    const float* __restrict__ bg, const float* __restrict__ bb,
    const float* __restrict__ bm, const float* __restrict__ bv)
{
    extern __shared__ char smraw[];
    char* smA = smraw + ((128 - (smem_to_u32(smraw) & 127)) & 127);
    const uint32_t sb = smem_to_u32(smA);
    __shared__ float s_sc[128], s_sh[128];

    const int t = threadIdx.x, wid = t >> 5, lane = t & 31;
    const int img = blockIdx.x / 56, oy = blockIdx.x % 56;

    if (t < 128) {
        float inv = rsqrtf(bv[t] + EPSS);
        float sc = bg[t]*inv;
        s_sc[t] = sc; s_sh[t] = bb[t] - bm[t]*sc;
    }

    // --- rolling loader state (per thread) ---
    const int c16 = t & 3;
    const int r   = t >> 2;
    const uint32_t soA = SWZ64((uint32_t)(r*64 + c16*16));
    const ptrdiff_t xlod = (const __half*)g_xp_lo - (const __half*)g_xp_hi;
    const __half* const xrow0 = g_xp_hi
        + ((size_t)(img*58 + oy))*(XPW*256) + c16*8 + (size_t)r*256;
    const __half* xp = xrow0;                       // chunk 0: ky=0,kx=0,cc=0
    const __half* wp = g_wb_hi + c16*8 + (size_t)r*64;
    int jn = 0;            // chunks issued so far
    int kxr = 0, kyr = 0;  // tap coords of the NEXT chunk after a tap boundary
    uint32_t dstg = 0;     // stage of next issue

    auto issue = [&]() {
        uint32_t st = sb + dstg*STG4;
        CP_ASYNC16(st +         soA, xp);
        CP_ASYNC16(st +  4096 + soA, xp + xlod);
        CP_ASYNC16(st +  8192 + soA, wp);
        CP_ASYNC16(st + 12288 + soA, wp + 4096);
        asm volatile("cp.async.commit_group;" ::: "memory");
        // advance state to next chunk
        jn++;
        dstg = (dstg + 1) & 3;
        if ((jn & 7) == 0) {
            kxr++; if (kxr == 3) { kxr = 0; kyr++; }
            xp = xrow0 + (kyr*XPW + kxr)*256;
        } else {
            xp += 32;
        }
        wp += (jn & 1) ? 32 : 8160;
    };

    const int wm = wid & 1, wn = wid >> 1;     // 2 m x 4 n warp grid, 32x32 tile
    float acc[2][4][4];
    #pragma unroll
    for (int a = 0; a < 2; a++)
        #pragma unroll
        for (int b = 0; b < 4; b++)
            #pragma unroll
            for (int c = 0; c < 4; c++) acc[a][b][c] = 0.f;

    const int lg = lane >> 3, lri = lane & 7;
    const int rsel = (lg & 1)*8 + lri;
    const int csel = (lg >> 1)*16;

    issue(); issue(); issue();
    for (int i = 0; i < NCH2; i++) {
        int rem = NCH2 - 1 - i;
        if (rem >= 2)      asm volatile("cp.async.wait_group 2;" ::: "memory");
        else if (rem == 1) asm volatile("cp.async.wait_group 1;" ::: "memory");
        else               asm volatile("cp.async.wait_group 0;" ::: "memory");
        __syncthreads();
        if (i + 3 < NCH2) issue();

        uint32_t base = sb + (i & 3)*STG4;
        #pragma unroll
        for (int ks = 0; ks < 2; ks++) {
            int cb = ks*32 + csel;
            uint32_t ah[2][4], al[2][4], bh[2][4];
            #pragma unroll
            for (int mf = 0; mf < 2; mf++) {
                int row = wm*32 + mf*16 + rsel;
                ldsm4(ah[mf], base + SWZ64((uint32_t)(row*64 + cb)));
            }
            #pragma unroll
            for (int nb = 0; nb < 2; nb++) {
                int row = wn*32 + nb*16 + rsel;
                ldsm4(bh[nb], base + 8192 + SWZ64((uint32_t)(row*64 + cb)));
            }
            #pragma unroll
            for (int mf = 0; mf < 2; mf++)
                #pragma unroll
                for (int nf = 0; nf < 4; nf++)
                    mma16816(acc[mf][nf], ah[mf], bh[nf>>1][nf&1], bh[nf>>1][(nf&1)+2]);
            #pragma unroll
            for (int mf = 0; mf < 2; mf++) {
                int row = wm*32 + mf*16 + rsel;
                ldsm4(al[mf], base + 4096 + SWZ64((uint32_t)(row*64 + cb)));
            }
            #pragma unroll
            for (int mf = 0; mf < 2; mf++)
                #pragma unroll
                for (int nf = 0; nf < 4; nf++)
                    mma16816(acc[mf][nf], al[mf], bh[nf>>1][nf&1], bh[nf>>1][(nf&1)+2]);
        }
    }

    // epilogue: BN + SiLU; fp32 NHWC store + fp16 hi/lo store for value GEMM
    const int ro = lane >> 2, co = (lane & 3) << 1;
    #pragma unroll
    for (int mf = 0; mf < 2; mf++) {
        #pragma unroll
        for (int half = 0; half < 2; half++) {
            int ox = wm*32 + mf*16 + half*8 + ro;
            if (ox < 56) {
                size_t pidbase = ((size_t)(img*HW + oy*WW + ox))*CM;
                float* dst = g_h + pidbase;
                #pragma unroll
                for (int nf = 0; nf < 4; nf++) {
                    int c = wn*32 + nf*8 + co;
                    float2 o2;
                    o2.x = siluf(acc[mf][nf][half*2+0]*s_sc[c]   + s_sh[c]);
                    o2.y = siluf(acc[mf][nf][half*2+1]*s_sc[c+1] + s_sh[c+1]);
                    *(float2*)(dst + c) = o2;
                    __half hx, lx, hy, ly;
                    split_h(o2.x, hx, lx);
                    split_h(o2.y, hy, ly);
                    *(__half2*)(g_hb_hi + pidbase + c) = __halves2half2(hx, hy);
                    *(__half2*)(g_hb_lo + pidbase + c) = __halves2half2(lx, ly);
                }
            }
        }
    }
}

// ===================== generic K=128 GEMM on mma.sync (fp16 2-term) =====================
// EPI 0/1: fp32 C + bias(split)   EPI 3: fp16 C + bias   EPI 2: NCHW resid epilogue
template<int EPI>
__global__ __launch_bounds__(256, 3) void gemm_tc(
    const __half* __restrict__ Ahi, const __half* __restrict__ Alo,
    const __half* __restrict__ Bhi,
    int Ntot, int Nout, int N1,
    const float* __restrict__ bias, const float* __restrict__ bias2,
    float* __restrict__ C,
    const float* __restrict__ eb,
    const float* __restrict__ bg, const float* __restrict__ bb,
    const float* __restrict__ bm, const float* __restrict__ bv,
    const float* __restrict__ resid)
{
    extern __shared__ char smraw[];
    char* smA = smraw + ((1024 - (smem_to_u32(smraw) & 1023)) & 1023);
    const uint32_t sbA = smem_to_u32(smA);   // A: 32KB [buf][kc][64m][128B]
    const uint32_t sbB = sbA + 32768;        // B: 32KB [kc][128n][128B]

    const int t = threadIdx.x, wid = t >> 5, lane = t & 31;
    const int m0 = blockIdx.x * 64;
    const int n0 = blockIdx.y * 128;

    #pragma unroll
    for (int i = 0; i < 8; i++) {
        int g = t*8 + i;
        int buf = g >> 10, kc = (g >> 9) & 1, m = (g >> 3) & 63, c16 = g & 7;
        const __half* src = (buf ? Alo : Ahi) + (size_t)(m0 + m)*128 + kc*64 + c16*8;
        CP_ASYNC16(sbA + buf*16384 + kc*8192 + SWZ128((uint32_t)(m*128 + c16*16)), src);
    }
    #pragma unroll
    for (int i = 0; i < 8; i++) {
        int g = t*8 + i;
        int kc = g >> 10, n = (g >> 3) & 127, c16 = g & 7;
        const __half* src = Bhi + ((size_t)kc*Ntot + n0 + n)*64 + c16*8;
        CP_ASYNC16(sbB + kc*16384 + SWZ128((uint32_t)(n*128 + c16*16)), src);
    }
    asm volatile("cp.async.commit_group;" ::: "memory");
    asm volatile("cp.async.wait_group 0;" ::: "memory");
    __syncthreads();

    const int wm = wid & 1, wn = wid >> 1;
    float acc[2][4][4];
    #pragma unroll
    for (int a = 0; a < 2; a++)
        #pragma unroll
        for (int b = 0; b < 4; b++)
            #pragma unroll
            for (int c = 0; c < 4; c++) acc[a][b][c] = 0.f;

    const int lg = lane >> 3, lri = lane & 7;
    const int rsel = (lg & 1)*8 + lri;
    const int csel = (lg >> 1)*16;

    #pragma unroll
    for (int kc = 0; kc < 2; kc++) {
        uint32_t aH = sbA +          kc*8192;
        uint32_t aL = sbA + 16384 +  kc*8192;
        uint32_t bH = sbB +          kc*16384;
        #pragma unroll
        for (int ks = 0; ks < 4; ks++) {
            int cb = ks*32 + csel;
            uint32_t ah[2][4], al[2][4], bf[2][4];
            #pragma unroll
            for (int mf = 0; mf < 2; mf++) {
                int row = wm*32 + mf*16 + rsel;
                ldsm4(ah[mf], aH + SWZ128((uint32_t)(row*128 + cb)));
            }
            #pragma unroll
            for (int nb = 0; nb < 2; nb++) {
                int row = wn*32 + nb*16 + rsel;
                ldsm4(bf[nb], bH + SWZ128((uint32_t)(row*128 + cb)));
            }
            #pragma unroll
            for (int mf = 0; mf < 2; mf++)
                #pragma unroll
                for (int nf = 0; nf < 4; nf++)
                    mma16816(acc[mf][nf], ah[mf], bf[nf>>1][nf&1], bf[nf>>1][(nf&1)+2]);
            #pragma unroll
            for (int mf = 0; mf < 2; mf++) {
                int row = wm*32 + mf*16 + rsel;
                ldsm4(al[mf], aL + SWZ128((uint32_t)(row*128 + cb)));
            }
            #pragma unroll
            for (int mf = 0; mf < 2; mf++)
                #pragma unroll
                for (int nf = 0; nf < 4; nf++)
                    mma16816(acc[mf][nf], al[mf], bf[nf>>1][nf&1], bf[nf>>1][(nf&1)+2]);
        }
    }

    const int ro = lane >> 2, co = (lane & 3) << 1;
    if (EPI != 2) {
        #pragma unroll
        for (int mf = 0; mf < 2; mf++) {
            #pragma unroll
            for (int half = 0; half < 2; half++) {
                int m = wm*32 + mf*16 + half*8 + ro;
                size_t rowb = (size_t)(m0 + m)*Nout;
                #pragma unroll
                for (int nf = 0; nf < 4; nf++) {
                    int c = n0 + wn*32 + nf*8 + co;
                    if (c < Nout) {
                        float b0 = (c   < N1) ? bias[c]   : ((c   < Nout) ? bias2[c-N1]   : 0.f);
                        float b1 = (c+1 < N1) ? bias[c+1] : ((c+1 < Nout) ? bias2[c+1-N1] : 0.f);
                        float ox = acc[mf][nf][half*2+0] + b0;
                        float oyv = acc[mf][nf][half*2+1] + b1;
                        if (EPI == 3) {
                            __half* Ch = (__half*)C;
                            *(__half2*)(Ch + rowb + c) =
                                __halves2half2(__float2half(ox), __float2half(oyv));
                        } else {
                            float2 o2; o2.x = ox; o2.y = oyv;
                            *(float2*)(C + rowb + c) = o2;
                        }
                    }
                }
            }
        }
    } else {
        __syncthreads();
        float* st = (float*)smA;
        #pragma unroll
        for (int mf = 0; mf < 2; mf++) {
            #pragma unroll
            for (int half = 0; half < 2; half++) {
                int m = wm*32 + mf*16 + half*8 + ro;
                #pragma unroll
                for (int nf = 0; nf < 4; nf++) {
                    int cl = wn*32 + nf*8 + co;
                    int c  = n0 + cl;
                    float inv0 = rsqrtf(bv[c] + EPSS);
                    float sc0  = bg[c]*inv0;
                    float v0 = (acc[mf][nf][half*2+0] + eb[c])*sc0 + (bb[c] - bm[c]*sc0);
                    float inv1 = rsqrtf(bv[c+1] + EPSS);
                    float sc1  = bg[c+1]*inv1;
                    float v1 = (acc[mf][nf][half*2+1] + eb[c+1])*sc1 + (bb[c+1] - bm[c+1]*sc1);
                    st[cl*66 + m]     = siluf(v0);
                    st[(cl+1)*66 + m] = siluf(v1);
                }
            }
        }
        __syncthreads();
        const int mloc = t & 63, nsub = t >> 6;
        const int mg = m0 + mloc;
        const int img = mg / HW;
        const int pp  = mg - img*HW;
        const size_t ob = (size_t)img*C2*HW + pp;
        #pragma unroll
        for (int i = 0; i < 32; i++) {
            int n = nsub + i*4;
            size_t adr = ob + (size_t)(n0 + n)*HW;
            C[adr] = resid[adr] + st[n*66 + mloc];
        }
    }
}

// ===================== depthwise + LN + GELU (warp per pixel) =====================
__global__ __launch_bounds__(128) void dw_ln_gelu(
    const float* __restrict__ wdw, const float* __restrict__ bdw,
    const float* __restrict__ lg,  const float* __restrict__ lb)
{
    __shared__ float s_w[9*128];
    __shared__ float s_b[128], s_g[128], s_lb[128];
    const int t = threadIdx.x;
    #pragma unroll
    for (int i = 0; i < 9; i++) s_w[i*128 + t] = wdw[t*9 + i];
    s_b[t] = bdw[t]; s_g[t] = lg[t]; s_lb[t] = lb[t];
    __syncthreads();

    const int warp = t >> 5, lane = t & 31;
    const int pix = blockIdx.x*4 + warp;
    const int img = pix / HW;
    const int p   = pix - img*HW;
    const int py  = p / WW, px = p - py*WW;
    const float* hb = g_h + (size_t)img*HW*CM;
    const int c0 = lane << 2;

    float sx = s_b[c0], sy = s_b[c0+1], sz = s_b[c0+2], sw = s_b[c0+3];
    #pragma unroll
    for (int ky = 0; ky < 3; ky++) {
        int yy = py + ky - 1;
        if ((unsigned)yy >= HH) continue;
        #pragma unroll
        for (int kx = 0; kx < 3; kx++) {
            int xx = px + kx - 1;
            if ((unsigned)xx >= WW) continue;
            float4 v = *(const float4*)(hb + (size_t)(yy*WW + xx)*CM + c0);
            const float* wk = s_w + (ky*3 + kx)*128 + c0;
            sx = fmaf(v.x, wk[0], sx);
            sy = fmaf(v.y, wk[1], sy);
            sz = fmaf(v.z, wk[2], sz);
            sw = fmaf(v.w, wk[3], sw);
        }
    }
    float r1 = sx + sy + sz + sw;
    float r2 = sx*sx + sy*sy + sz*sz + sw*sw;
    #pragma unroll
    for (int o = 16; o; o >>= 1) {
        r1 += __shfl_xor_sync(0xffffffffu, r1, o);
        r2 += __shfl_xor_sync(0xffffffffu, r2, o);
    }
    float mu  = r1 * (1.f/CM);
    float var = r2 * (1.f/CM) - mu*mu;
    float rs  = rsqrtf(var + EPSS);
    float vv[4] = {sx, sy, sz, sw};
    __half hs[4], ls[4];
    #pragma unroll
    for (int j = 0; j < 4; j++) {
        float tn = (vv[j] - mu)*rs*s_g[c0+j] + s_lb[c0+j];
        float ge = 0.5f*tn*(1.f + erff(tn*0.70710678118654752f));
        split_h(ge, hs[j], ls[j]);
    }
    size_t a = (size_t)pix*CM + c0;
    *(__half2*)(g_tb_hi + a)     = __halves2half2(hs[0], hs[1]);
    *(__half2*)(g_tb_hi + a + 2) = __halves2half2(hs[2], hs[3]);
    *(__half2*)(g_tb_lo + a)     = __halves2half2(ls[0], ls[1]);
    *(__half2*)(g_tb_lo + a + 2) = __halves2half2(ls[2], ls[3]);
}

// ===================== DCNv3 sampler (warp softmax, fp16 value) =====================
__global__ __launch_bounds__(256) void dcn_core()
{
    int gw   = (blockIdx.x*blockDim.x + threadIdx.x) >> 5;
    int lane = threadIdx.x & 31;
    if (gw >= NPIX*GG) return;
    int pid = gw >> 2;
    int g   = gw & 3;
    int img = pid / HW;
    int p   = pid - img*HW;
    int iy  = p / WW;
    int ix  = p - iy*WW;

    const float* om = g_om + (size_t)pid*NOM;
    float lgt = (lane < 9) ? om[72 + g*9 + lane] : -1e30f;
    float mx = lgt;
    #pragma unroll
    for (int o = 16; o; o >>= 1) mx = fmaxf(mx, __shfl_xor_sync(0xffffffffu, mx, o));
    float e = (lane < 9) ? expf(lgt - mx) : 0.f;
    float se = e;
    #pragma unroll
    for (int o = 16; o; o >>= 1) se += __shfl_xor_sync(0xffffffffu, se, o);
    float inv = 1.f / se;

    const __half* vb = g_v + (size_t)img*HW*CM + g*GC + lane;
    float acc = 0.f;
    #pragma unroll
    for (int k = 0; k < 9; k++) {
        float mk = __shfl_sync(0xffffffffu, e, k) * inv;
        float dx = om[(g*9 + k)*2];
        float dy = om[(g*9 + k)*2 + 1];
        int kxi = k / 3;
        int kyi = k - kxi*3;
        float fx = (float)(ix + kxi) + dx;
        float fy = (float)(iy + kyi) + dy;
        float x0f = floorf(fx), y0f = floorf(fy);
        float wx = fx - x0f, wy = fy - y0f;
        int xm = (int)x0f - 1, ym = (int)y0f - 1;
        float v00 = 0.f, v01 = 0.f, v10 = 0.f, v11 = 0.f;
        bool vx0 = (unsigned)xm     < WW;
        bool vx1 = (unsigned)(xm+1) < WW;
        bool vy0 = (unsigned)ym     < HH;
        bool vy1 = (unsigned)(ym+1) < HH;
        if (vy0 && vx0) v00 = __half2float(vb[(size_t)(ym*WW + xm      )*CM]);
        if (vy0 && vx1) v01 = __half2float(vb[(size_t)(ym*WW + xm + 1  )*CM]);
        if (vy1 && vx0) v10 = __half2float(vb[(size_t)((ym+1)*WW + xm  )*CM]);
        if (vy1 && vx1) v11 = __half2float(vb[(size_t)((ym+1)*WW + xm+1)*CM]);
        float sv = v00*(1.f-wy)*(1.f-wx) + v01*(1.f-wy)*wx
                 + v10*wy*(1.f-wx)       + v11*wy*wx;
        acc = fmaf(mk, sv, acc);
    }
    size_t oidx = (size_t)pid*CM + g*GC + lane;
    split_h(acc, g_ob_hi[oidx], g_ob_lo[oidx]);
}

// ===================== launch =====================
extern "C" void kernel_launch(void* const* d_in, const int* in_sizes, int n_in,
                              void* d_out, int out_size)
{
    const float* x    = (const float*)d_in[0];
    const float* wcv1 = (const float*)d_in[1];
    const float* bn1g = (const float*)d_in[2];
    const float* bn1b = (const float*)d_in[3];
    const float* bn1m = (const float*)d_in[4];
    const float* bn1v = (const float*)d_in[5];
    const float* wdw  = (const float*)d_in[6];
    const float* bdw  = (const float*)d_in[7];
    const float* lng  = (const float*)d_in[8];
    const float* lnb  = (const float*)d_in[9];
    const float* winp = (const float*)d_in[10];
    const float* binp = (const float*)d_in[11];
    const float* woff = (const float*)d_in[12];
    const float* boff = (const float*)d_in[13];
    const float* wmsk = (const float*)d_in[14];
    const float* bmsk = (const float*)d_in[15];
    const float* wout = (const float*)d_in[16];
    const float* bout = (const float*)d_in[17];
    const float* bn2g = (const float*)d_in[18];
    const float* bn2b = (const float*)d_in[19];
    const float* bn2m = (const float*)d_in[20];
    const float* bn2v = (const float*)d_in[21];
    float* out = (float*)d_out;

    float *pom;
    __half *pv;
    cudaGetSymbolAddress((void**)&pv,  g_v);
    cudaGetSymbolAddress((void**)&pom, g_om);
    __half *hbh, *hbl, *tbh, *tbl, *obh, *obl, *wvh, *womh, *woh;
    cudaGetSymbolAddress((void**)&hbh, g_hb_hi); cudaGetSymbolAddress((void**)&hbl, g_hb_lo);
    cudaGetSymbolAddress((void**)&tbh, g_tb_hi); cudaGetSymbolAddress((void**)&tbl, g_tb_lo);
    cudaGetSymbolAddress((void**)&obh, g_ob_hi); cudaGetSymbolAddress((void**)&obl, g_ob_lo);
    cudaGetSymbolAddress((void**)&wvh, g_wv_hi);
    cudaGetSymbolAddress((void**)&womh, g_wom_hi);
    cudaGetSymbolAddress((void**)&woh, g_wo_hi);

    const int smem_conv = NSTG*STG4 + 128;    // 65,664 B -> 3 CTAs/SM
    const int smem_gemm = 64*1024 + 1024;
    cudaFuncSetAttribute(conv1_mma, cudaFuncAttributeMaxDynamicSharedMemorySize, smem_conv);
    cudaFuncSetAttribute(gemm_tc<3>, cudaFuncAttributeMaxDynamicSharedMemorySize, smem_gemm);
    cudaFuncSetAttribute(gemm_tc<1>, cudaFuncAttributeMaxDynamicSharedMemorySize, smem_gemm);
    cudaFuncSetAttribute(gemm_tc<2>, cudaFuncAttributeMaxDynamicSharedMemorySize, smem_gemm);

    xprep<<<8*58, 256>>>(x);                                  // 1
    wprep<<<(36*128*64 + 255)/256, 256>>>(wcv1);              // 2
    prep_all<<<256, 256>>>(winp, woff, wmsk, wout);           // 3
    conv1_mma<<<8*56, 256, smem_conv>>>(bn1g, bn1b, bn1m, bn1v);  // 4 <- ncu capture slot
    dw_ln_gelu<<<NPIX/4, 128>>>(wdw, bdw, lng, lnb);

    // value projection -> g_v (fp16)
    gemm_tc<3><<<dim3(NPIX/64, 1), 256, smem_gemm>>>(hbh, hbl, wvh,
        128, 128, 128, binp, nullptr, (float*)pv,
        nullptr, nullptr, nullptr, nullptr, nullptr, nullptr);
    gemm_tc<1><<<dim3(NPIX/64, 1), 256, smem_gemm>>>(tbh, tbl, womh,
        128, NOM, 72, boff, bmsk, pom,
        nullptr, nullptr, nullptr, nullptr, nullptr, nullptr);
    dcn_core<<<(NPIX*GG)/8, 256>>>();
    gemm_tc<2><<<dim3(NPIX/64, 2), 256, smem_gemm>>>(obh, obl, woh,
        256, 256, 256, nullptr, nullptr, out,
        bout, bn2g, bn2b, bn2m, bn2v, x);
}

// round 12
// speedup vs baseline: 1.2269x; 1.2269x over previous
#include <cuda_runtime.h>
#include <cuda_fp16.h>
#include <math.h>
#include <stdint.h>

#define NB   8
#define C1   256
#define C2   256
#define CM   128
#define HH   56
#define WW   56
#define HW   3136
#define NPIX (NB*HW)
#define GG   4
#define GC   32
#define EPSS 1e-5f
#define NOM  108
#define NCH2 72          // 72 K-chunks of 32
#define NSTG 4
#define XPW  66
#define STG1 12288       // stage: A 4KB + B 8KB

// scratch (device globals: allocation-free rule)
__device__ float g_h [NPIX*CM];
__device__ __half g_v [NPIX*CM];
__device__ float g_om[NPIX*NOM];
__device__ __half g_xp[8*58*XPW*256];
__device__ __half g_wb[36*128*64];
// fp16 A-operands for the K=128 GEMMs
__device__ __half g_hb[NPIX*CM];
__device__ __half g_tb[NPIX*CM];
__device__ __half g_ob[NPIX*CM];
// B operands, layout [kc(2)][n][64 k], k-major rows
__device__ __half g_wv [2*128*64];
__device__ __half g_wom[2*128*64];
__device__ __half g_wo [2*256*64];

__device__ __forceinline__ float siluf(float v){ return v / (1.f + expf(-v)); }

__device__ __forceinline__ uint32_t smem_to_u32(const void* p) {
    uint32_t a;
    asm("{ .reg .u64 t; cvta.to.shared.u64 t, %1; cvt.u32.u64 %0, t; }" : "=r"(a) : "l"(p));
    return a;
}
#define SWZ128(o) ((o) ^ (((o) >> 3) & 0x70))
#define SWZ64(o)  ((o) ^ (((o) >> 3) & 0x30))
#define CP_ASYNC16(sa, gp) \
    asm volatile("cp.async.cg.shared.global [%0], [%1], 16;" \
        :: "r"((uint32_t)(sa)), "l"(gp) : "memory")

__device__ __forceinline__ void ldsm4(uint32_t* r, uint32_t addr) {
    asm volatile("ldmatrix.sync.aligned.m8n8.x4.shared.b16 {%0,%1,%2,%3}, [%4];"
        : "=r"(r[0]), "=r"(r[1]), "=r"(r[2]), "=r"(r[3]) : "r"(addr));
}
__device__ __forceinline__ void mma16816(float* d, const uint32_t* a, uint32_t b0, uint32_t b1) {
    asm volatile("mma.sync.aligned.m16n8k16.row.col.f32.f16.f16.f32 "
        "{%0,%1,%2,%3}, {%4,%5,%6,%7}, {%8,%9}, {%0,%1,%2,%3};"
        : "+f"(d[0]), "+f"(d[1]), "+f"(d[2]), "+f"(d[3])
        : "r"(a[0]), "r"(a[1]), "r"(a[2]), "r"(a[3]), "r"(b0), "r"(b1));
}

// ===================== prep: pad/transpose x =====================
__global__ __launch_bounds__(256) void xprep(const float* __restrict__ x)
{
    const int b = blockIdx.x, img = b / 58, yp = b % 58;
    const size_t rowbase = ((size_t)img*58 + yp) * (XPW*256);
    const int t = threadIdx.x;
    uint2 z2 = make_uint2(0u, 0u);
    for (int i = t; i < XPW*256/4; i += 256)
        ((uint2*)(g_xp + rowbase))[i] = z2;
    if (yp == 0 || yp == 57) return;
    __syncthreads();
    const int oy = yp - 1;
    __shared__ float sm[128*57];
    for (int pass = 0; pass < 2; pass++) {
        for (int i = t; i < 128*56; i += 256) {
            int c = i / 56, ox = i % 56;
            sm[c*57 + ox] = x[((size_t)(img*256 + pass*128 + c))*HW + oy*WW + ox];
        }
        __syncthreads();
        for (int i = t; i < 56*128; i += 256) {
            int ox = i >> 7, c = i & 127;
            g_xp[rowbase + (size_t)(ox+1)*256 + pass*128 + c] = __float2half(sm[c*57 + ox]);
        }
        __syncthreads();
    }
}

// conv weights: w[o][c*9+tap] -> [chunk64=tap*4+cc][o][ci]
__global__ __launch_bounds__(256) void wprep(const float* __restrict__ w)
{
    int idx = blockIdx.x*256 + threadIdx.x;
    if (idx >= 36*128*64) return;
    int ci = idx & 63, o = (idx >> 6) & 127, ch = idx >> 13;
    int tap = ch >> 2, cc = ch & 3;
    g_wb[idx] = __float2half(w[(size_t)o*2304 + (cc*64 + ci)*9 + tap]);
}

// fused GEMM-weight preps: wv (128), wom (72|36), wo (256)
__global__ __launch_bounds__(256) void prep_all(
    const float* __restrict__ winp, const float* __restrict__ woff,
    const float* __restrict__ wmsk, const float* __restrict__ wout)
{
    int idx = blockIdx.x*256 + threadIdx.x;   // 0 .. 65535
    const float* w1; const float* w2; int n1, n2, Ntot, li;
    __half* dhi;
    if (idx < 16384)      { li = idx;        w1 = winp; w2 = nullptr; n1 = 128; n2 = 0;  Ntot = 128; dhi = g_wv;  }
    else if (idx < 32768) { li = idx-16384;  w1 = woff; w2 = wmsk;    n1 = 72;  n2 = 36; Ntot = 128; dhi = g_wom; }
    else                  { li = idx-32768;  w1 = wout; w2 = nullptr; n1 = 256; n2 = 0;  Ntot = 256; dhi = g_wo;  }
    int ki = li & 63;
    int n  = (li >> 6) % Ntot;
    int kc = li / (64*Ntot);
    int k  = kc*64 + ki;
    float v = 0.f;
    if (n < n1)           v = w1[(size_t)k*n1 + n];
    else if (n < n1 + n2) v = w2[(size_t)k*n2 + (n - n1)];
    dhi[li] = __float2half(v);
}

// ===================== conv1 via mma.sync fp16 =====================
// CTA = (img, 1 output row): M=64, N=128, K = 72 chunks of 32.
// Stage 12KB (A 4KB, B 8KB, 64B rows SW64), NSTG=4 -> 48KB -> 4 CTAs/SM.
__global__ __launch_bounds__(256, 4) void conv1_mma(
    const float* __restrict__ bg, const float* __restrict__ bb,
    const float* __restrict__ bm, const float* __restrict__ bv)
{
    extern __shared__ char smraw[];
    char* smA = smraw + ((128 - (smem_to_u32(smraw) & 127)) & 127);
    const uint32_t sb = smem_to_u32(smA);
    __shared__ float s_sc[128], s_sh[128];

    const int t = threadIdx.x, wid = t >> 5, lane = t & 31;
    const int img = blockIdx.x / 56, oy = blockIdx.x % 56;

    if (t < 128) {
        float inv = rsqrtf(bv[t] + EPSS);
        float sc = bg[t]*inv;
        s_sc[t] = sc; s_sh[t] = bb[t] - bm[t]*sc;
    }

    // rolling loader: 3 cp.async per thread per chunk
    const int c16 = t & 3;
    const int r   = t >> 2;
    const uint32_t soA = SWZ64((uint32_t)(r*64 + c16*16));
    const __half* const xrow0 = g_xp
        + ((size_t)(img*58 + oy))*(XPW*256) + c16*8 + (size_t)r*256;
    const __half* xp = xrow0;
    const __half* wp = g_wb + c16*8 + (size_t)r*64;
    int jn = 0;
    int kxr = 0, kyr = 0;
    uint32_t dstg = 0;

    auto issue = [&]() {
        uint32_t st = sb + dstg*STG1;
        CP_ASYNC16(st +        soA, xp);
        CP_ASYNC16(st + 4096 + soA, wp);
        CP_ASYNC16(st + 8192 + soA, wp + 4096);
        asm volatile("cp.async.commit_group;" ::: "memory");
        jn++;
        dstg = (dstg + 1) & 3;
        if ((jn & 7) == 0) {
            kxr++; if (kxr == 3) { kxr = 0; kyr++; }
            xp = xrow0 + (kyr*XPW + kxr)*256;
        } else {
            xp += 32;
        }
        wp += (jn & 1) ? 32 : 8160;
    };

    const int wm = wid & 1, wn = wid >> 1;
    float acc[2][4][4];
    #pragma unroll
    for (int a = 0; a < 2; a++)
        #pragma unroll
        for (int b = 0; b < 4; b++)
            #pragma unroll
            for (int c = 0; c < 4; c++) acc[a][b][c] = 0.f;

    const int lg = lane >> 3, lri = lane & 7;
    const int rsel = (lg & 1)*8 + lri;
    const int csel = (lg >> 1)*16;

    issue(); issue(); issue();
    for (int i = 0; i < NCH2; i++) {
        int rem = NCH2 - 1 - i;
        if (rem >= 2)      asm volatile("cp.async.wait_group 2;" ::: "memory");
        else if (rem == 1) asm volatile("cp.async.wait_group 1;" ::: "memory");
        else               asm volatile("cp.async.wait_group 0;" ::: "memory");
        __syncthreads();
        if (i + 3 < NCH2) issue();

        uint32_t base = sb + (i & 3)*STG1;
        #pragma unroll
        for (int ks = 0; ks < 2; ks++) {
            int cb = ks*32 + csel;
            uint32_t ah[2][4], bh[2][4];
            #pragma unroll
            for (int mf = 0; mf < 2; mf++) {
                int row = wm*32 + mf*16 + rsel;
                ldsm4(ah[mf], base + SWZ64((uint32_t)(row*64 + cb)));
            }
            #pragma unroll
            for (int nb = 0; nb < 2; nb++) {
                int row = wn*32 + nb*16 + rsel;
                ldsm4(bh[nb], base + 4096 + SWZ64((uint32_t)(row*64 + cb)));
            }
            #pragma unroll
            for (int mf = 0; mf < 2; mf++)
                #pragma unroll
                for (int nf = 0; nf < 4; nf++)
                    mma16816(acc[mf][nf], ah[mf], bh[nf>>1][nf&1], bh[nf>>1][(nf&1)+2]);
        }
    }

    // epilogue: BN + SiLU; fp32 NHWC + fp16 store for value GEMM
    const int ro = lane >> 2, co = (lane & 3) << 1;
    #pragma unroll
    for (int mf = 0; mf < 2; mf++) {
        #pragma unroll
        for (int half = 0; half < 2; half++) {
            int ox = wm*32 + mf*16 + half*8 + ro;
            if (ox < 56) {
                size_t pidbase = ((size_t)(img*HW + oy*WW + ox))*CM;
                float* dst = g_h + pidbase;
                #pragma unroll
                for (int nf = 0; nf < 4; nf++) {
                    int c = wn*32 + nf*8 + co;
                    float2 o2;
                    o2.x = siluf(acc[mf][nf][half*2+0]*s_sc[c]   + s_sh[c]);
                    o2.y = siluf(acc[mf][nf][half*2+1]*s_sc[c+1] + s_sh[c+1]);
                    *(float2*)(dst + c) = o2;
                    *(__half2*)(g_hb + pidbase + c) =
                        __halves2half2(__float2half(o2.x), __float2half(o2.y));
                }
            }
        }
    }
}

// ===================== generic K=128 GEMM on mma.sync (fp16) =====================
// EPI 1: fp32 C + bias(split)  EPI 3: fp16 C + bias  EPI 2: NCHW resid epilogue
template<int EPI>
__global__ __launch_bounds__(256, 4) void gemm_tc(
    const __half* __restrict__ Ahi, const __half* __restrict__ Bhi,
    int Ntot, int Nout, int N1,
    const float* __restrict__ bias, const float* __restrict__ bias2,
    float* __restrict__ C,
    const float* __restrict__ eb,
    const float* __restrict__ bg, const float* __restrict__ bb,
    const float* __restrict__ bm, const float* __restrict__ bv,
    const float* __restrict__ resid)
{
    extern __shared__ char smraw[];
    char* smA = smraw + ((1024 - (smem_to_u32(smraw) & 1023)) & 1023);
    const uint32_t sbA = smem_to_u32(smA);   // A: 16KB [kc][64m][128B]
    const uint32_t sbB = sbA + 16384;        // B: 32KB [kc][128n][128B]

    const int t = threadIdx.x, wid = t >> 5, lane = t & 31;
    const int m0 = blockIdx.x * 64;
    const int n0 = blockIdx.y * 128;

    #pragma unroll
    for (int i = 0; i < 4; i++) {
        int g = t*4 + i;
        int kc = g >> 9, m = (g >> 3) & 63, c16 = g & 7;
        const __half* src = Ahi + (size_t)(m0 + m)*128 + kc*64 + c16*8;
        CP_ASYNC16(sbA + kc*8192 + SWZ128((uint32_t)(m*128 + c16*16)), src);
    }
    #pragma unroll
    for (int i = 0; i < 8; i++) {
        int g = t*8 + i;
        int kc = g >> 10, n = (g >> 3) & 127, c16 = g & 7;
        const __half* src = Bhi + ((size_t)kc*Ntot + n0 + n)*64 + c16*8;
        CP_ASYNC16(sbB + kc*16384 + SWZ128((uint32_t)(n*128 + c16*16)), src);
    }
    asm volatile("cp.async.commit_group;" ::: "memory");
    asm volatile("cp.async.wait_group 0;" ::: "memory");
    __syncthreads();

    const int wm = wid & 1, wn = wid >> 1;
    float acc[2][4][4];
    #pragma unroll
    for (int a = 0; a < 2; a++)
        #pragma unroll
        for (int b = 0; b < 4; b++)
            #pragma unroll
            for (int c = 0; c < 4; c++) acc[a][b][c] = 0.f;

    const int lg = lane >> 3, lri = lane & 7;
    const int rsel = (lg & 1)*8 + lri;
    const int csel = (lg >> 1)*16;

    #pragma unroll
    for (int kc = 0; kc < 2; kc++) {
        uint32_t aH = sbA + kc*8192;
        uint32_t bH = sbB + kc*16384;
        #pragma unroll
        for (int ks = 0; ks < 4; ks++) {
            int cb = ks*32 + csel;
            uint32_t ah[2][4], bf[2][4];
            #pragma unroll
            for (int mf = 0; mf < 2; mf++) {
                int row = wm*32 + mf*16 + rsel;
                ldsm4(ah[mf], aH + SWZ128((uint32_t)(row*128 + cb)));
            }
            #pragma unroll
            for (int nb = 0; nb < 2; nb++) {
                int row = wn*32 + nb*16 + rsel;
                ldsm4(bf[nb], bH + SWZ128((uint32_t)(row*128 + cb)));
            }
            #pragma unroll
            for (int mf = 0; mf < 2; mf++)
                #pragma unroll
                for (int nf = 0; nf < 4; nf++)
                    mma16816(acc[mf][nf], ah[mf], bf[nf>>1][nf&1], bf[nf>>1][(nf&1)+2]);
        }
    }

    const int ro = lane >> 2, co = (lane & 3) << 1;
    if (EPI != 2) {
        #pragma unroll
        for (int mf = 0; mf < 2; mf++) {
            #pragma unroll
            for (int half = 0; half < 2; half++) {
                int m = wm*32 + mf*16 + half*8 + ro;
                size_t rowb = (size_t)(m0 + m)*Nout;
                #pragma unroll
                for (int nf = 0; nf < 4; nf++) {
                    int c = n0 + wn*32 + nf*8 + co;
                    if (c < Nout) {
                        float b0 = (c   < N1) ? bias[c]   : ((c   < Nout) ? bias2[c-N1]   : 0.f);
                        float b1 = (c+1 < N1) ? bias[c+1] : ((c+1 < Nout) ? bias2[c+1-N1] : 0.f);
                        float ox = acc[mf][nf][half*2+0] + b0;
                        float oyv = acc[mf][nf][half*2+1] + b1;
                        if (EPI == 3) {
                            __half* Ch = (__half*)C;
                            *(__half2*)(Ch + rowb + c) =
                                __halves2half2(__float2half(ox), __float2half(oyv));
                        } else {
                            float2 o2; o2.x = ox; o2.y = oyv;
                            *(float2*)(C + rowb + c) = o2;
                        }
                    }
                }
            }
        }
    } else {
        __syncthreads();
        float* st = (float*)smA;   // 128*66*4 = 33792 B <= 48KB
        #pragma unroll
        for (int mf = 0; mf < 2; mf++) {
            #pragma unroll
            for (int half = 0; half < 2; half++) {
                int m = wm*32 + mf*16 + half*8 + ro;
                #pragma unroll
                for (int nf = 0; nf < 4; nf++) {
                    int cl = wn*32 + nf*8 + co;
                    int c  = n0 + cl;
                    float inv0 = rsqrtf(bv[c] + EPSS);
                    float sc0  = bg[c]*inv0;
                    float v0 = (acc[mf][nf][half*2+0] + eb[c])*sc0 + (bb[c] - bm[c]*sc0);
                    float inv1 = rsqrtf(bv[c+1] + EPSS);
                    float sc1  = bg[c+1]*inv1;
                    float v1 = (acc[mf][nf][half*2+1] + eb[c+1])*sc1 + (bb[c+1] - bm[c+1]*sc1);
                    st[cl*66 + m]     = siluf(v0);
                    st[(cl+1)*66 + m] = siluf(v1);
                }
            }
        }
        __syncthreads();
        const int mloc = t & 63, nsub = t >> 6;
        const int mg = m0 + mloc;
        const int img = mg / HW;
        const int pp  = mg - img*HW;
        const size_t ob = (size_t)img*C2*HW + pp;
        #pragma unroll
        for (int i = 0; i < 32; i++) {
            int n = nsub + i*4;
            size_t adr = ob + (size_t)(n0 + n)*HW;
            C[adr] = resid[adr] + st[n*66 + mloc];
        }
    }
}

// ===================== depthwise + LN + GELU (warp per pixel) =====================
__global__ __launch_bounds__(128) void dw_ln_gelu(
    const float* __restrict__ wdw, const float* __restrict__ bdw,
    const float* __restrict__ lg,  const float* __restrict__ lb)
{
    __shared__ float s_w[9*128];
    __shared__ float s_b[128], s_g[128], s_lb[128];
    const int t = threadIdx.x;
    #pragma unroll
    for (int i = 0; i < 9; i++) s_w[i*128 + t] = wdw[t*9 + i];
    s_b[t] = bdw[t]; s_g[t] = lg[t]; s_lb[t] = lb[t];
    __syncthreads();

    const int warp = t >> 5, lane = t & 31;
    const int pix = blockIdx.x*4 + warp;
    const int img = pix / HW;
    const int p   = pix - img*HW;
    const int py  = p / WW, px = p - py*WW;
    const float* hb = g_h + (size_t)img*HW*CM;
    const int c0 = lane << 2;

    float sx = s_b[c0], sy = s_b[c0+1], sz = s_b[c0+2], sw = s_b[c0+3];
    #pragma unroll
    for (int ky = 0; ky < 3; ky++) {
        int yy = py + ky - 1;
        if ((unsigned)yy >= HH) continue;
        #pragma unroll
        for (int kx = 0; kx < 3; kx++) {
            int xx = px + kx - 1;
            if ((unsigned)xx >= WW) continue;
            float4 v = *(const float4*)(hb + (size_t)(yy*WW + xx)*CM + c0);
            const float* wk = s_w + (ky*3 + kx)*128 + c0;
            sx = fmaf(v.x, wk[0], sx);
            sy = fmaf(v.y, wk[1], sy);
            sz = fmaf(v.z, wk[2], sz);
            sw = fmaf(v.w, wk[3], sw);
        }
    }
    float r1 = sx + sy + sz + sw;
    float r2 = sx*sx + sy*sy + sz*sz + sw*sw;
    #pragma unroll
    for (int o = 16; o; o >>= 1) {
        r1 += __shfl_xor_sync(0xffffffffu, r1, o);
        r2 += __shfl_xor_sync(0xffffffffu, r2, o);
    }
    float mu  = r1 * (1.f/CM);
    float var = r2 * (1.f/CM) - mu*mu;
    float rs  = rsqrtf(var + EPSS);
    float vv[4] = {sx, sy, sz, sw};
    __half hs[4];
    #pragma unroll
    for (int j = 0; j < 4; j++) {
        float tn = (vv[j] - mu)*rs*s_g[c0+j] + s_lb[c0+j];
        float ge = 0.5f*tn*(1.f + erff(tn*0.70710678118654752f));
        hs[j] = __float2half(ge);
    }
    size_t a = (size_t)pix*CM + c0;
    *(__half2*)(g_tb + a)     = __halves2half2(hs[0], hs[1]);
    *(__half2*)(g_tb + a + 2) = __halves2half2(hs[2], hs[3]);
}

// ===================== DCNv3 sampler (warp softmax, fp16 value) =====================
__global__ __launch_bounds__(256) void dcn_core()
{
    int gw   = (blockIdx.x*blockDim.x + threadIdx.x) >> 5;
    int lane = threadIdx.x & 31;
    if (gw >= NPIX*GG) return;
    int pid = gw >> 2;
    int g   = gw & 3;
    int img = pid / HW;
    int p   = pid - img*HW;
    int iy  = p / WW;
    int ix  = p - iy*WW;

    const float* om = g_om + (size_t)pid*NOM;
    float lgt = (lane < 9) ? om[72 + g*9 + lane] : -1e30f;
    float mx = lgt;
    #pragma unroll
    for (int o = 16; o; o >>= 1) mx = fmaxf(mx, __shfl_xor_sync(0xffffffffu, mx, o));
    float e = (lane < 9) ? expf(lgt - mx) : 0.f;
    float se = e;
    #pragma unroll
    for (int o = 16; o; o >>= 1) se += __shfl_xor_sync(0xffffffffu, se, o);
    float inv = 1.f / se;

    const __half* vb = g_v + (size_t)img*HW*CM + g*GC + lane;
    float acc = 0.f;
    #pragma unroll
    for (int k = 0; k < 9; k++) {
        float mk = __shfl_sync(0xffffffffu, e, k) * inv;
        float dx = om[(g*9 + k)*2];
        float dy = om[(g*9 + k)*2 + 1];
        int kxi = k / 3;
        int kyi = k - kxi*3;
        float fx = (float)(ix + kxi) + dx;
        float fy = (float)(iy + kyi) + dy;
        float x0f = floorf(fx), y0f = floorf(fy);
        float wx = fx - x0f, wy = fy - y0f;
        int xm = (int)x0f - 1, ym = (int)y0f - 1;
        float v00 = 0.f, v01 = 0.f, v10 = 0.f, v11 = 0.f;
        bool vx0 = (unsigned)xm     < WW;
        bool vx1 = (unsigned)(xm+1) < WW;
        bool vy0 = (unsigned)ym     < HH;
        bool vy1 = (unsigned)(ym+1) < HH;
        if (vy0 && vx0) v00 = __half2float(vb[(size_t)(ym*WW + xm      )*CM]);
        if (vy0 && vx1) v01 = __half2float(vb[(size_t)(ym*WW + xm + 1  )*CM]);
        if (vy1 && vx0) v10 = __half2float(vb[(size_t)((ym+1)*WW + xm  )*CM]);
        if (vy1 && vx1) v11 = __half2float(vb[(size_t)((ym+1)*WW + xm+1)*CM]);
        float sv = v00*(1.f-wy)*(1.f-wx) + v01*(1.f-wy)*wx
                 + v10*wy*(1.f-wx)       + v11*wy*wx;
        acc = fmaf(mk, sv, acc);
    }
    g_ob[(size_t)pid*CM + g*GC + lane] = __float2half(acc);
}

// ===================== launch =====================
extern "C" void kernel_launch(void* const* d_in, const int* in_sizes, int n_in,
                              void* d_out, int out_size)
{
    const float* x    = (const float*)d_in[0];
    const float* wcv1 = (const float*)d_in[1];
    const float* bn1g = (const float*)d_in[2];
    const float* bn1b = (const float*)d_in[3];
    const float* bn1m = (const float*)d_in[4];
    const float* bn1v = (const float*)d_in[5];
    const float* wdw  = (const float*)d_in[6];
    const float* bdw  = (const float*)d_in[7];
    const float* lng  = (const float*)d_in[8];
    const float* lnb  = (const float*)d_in[9];
    const float* winp = (const float*)d_in[10];
    const float* binp = (const float*)d_in[11];
    const float* woff = (const float*)d_in[12];
    const float* boff = (const float*)d_in[13];
    const float* wmsk = (const float*)d_in[14];
    const float* bmsk = (const float*)d_in[15];
    const float* wout = (const float*)d_in[16];
    const float* bout = (const float*)d_in[17];
    const float* bn2g = (const float*)d_in[18];
    const float* bn2b = (const float*)d_in[19];
    const float* bn2m = (const float*)d_in[20];
    const float* bn2v = (const float*)d_in[21];
    float* out = (float*)d_out;

    float *pom;
    __half *pv;
    cudaGetSymbolAddress((void**)&pv,  g_v);
    cudaGetSymbolAddress((void**)&pom, g_om);
    __half *hb, *tb, *ob, *wv, *womp, *wo;
    cudaGetSymbolAddress((void**)&hb, g_hb);
    cudaGetSymbolAddress((void**)&tb, g_tb);
    cudaGetSymbolAddress((void**)&ob, g_ob);
    cudaGetSymbolAddress((void**)&wv, g_wv);
    cudaGetSymbolAddress((void**)&womp, g_wom);
    cudaGetSymbolAddress((void**)&wo, g_wo);

    const int smem_conv = NSTG*STG1 + 128;    // 49,280 B -> 4 CTAs/SM
    const int smem_gemm = 48*1024 + 1024;
    cudaFuncSetAttribute(conv1_mma, cudaFuncAttributeMaxDynamicSharedMemorySize, smem_conv);
    cudaFuncSetAttribute(gemm_tc<3>, cudaFuncAttributeMaxDynamicSharedMemorySize, smem_gemm);
    cudaFuncSetAttribute(gemm_tc<1>, cudaFuncAttributeMaxDynamicSharedMemorySize, smem_gemm);
    cudaFuncSetAttribute(gemm_tc<2>, cudaFuncAttributeMaxDynamicSharedMemorySize, smem_gemm);

    xprep<<<8*58, 256>>>(x);                                  // 1
    wprep<<<(36*128*64 + 255)/256, 256>>>(wcv1);              // 2
    prep_all<<<256, 256>>>(winp, woff, wmsk, wout);           // 3
    conv1_mma<<<8*56, 256, smem_conv>>>(bn1g, bn1b, bn1m, bn1v);  // 4 <- ncu capture slot
    dw_ln_gelu<<<NPIX/4, 128>>>(wdw, bdw, lng, lnb);

    // value projection -> g_v (fp16)
    gemm_tc<3><<<dim3(NPIX/64, 1), 256, smem_gemm>>>(hb, wv,
        128, 128, 128, binp, nullptr, (float*)pv,
        nullptr, nullptr, nullptr, nullptr, nullptr, nullptr);
    gemm_tc<1><<<dim3(NPIX/64, 1), 256, smem_gemm>>>(tb, womp,
        128, NOM, 72, boff, bmsk, pom,
        nullptr, nullptr, nullptr, nullptr, nullptr, nullptr);
    dcn_core<<<(NPIX*GG)/8, 256>>>();
    gemm_tc<2><<<dim3(NPIX/64, 2), 256, smem_gemm>>>(ob, wo,
        256, 256, 256, nullptr, nullptr, out,
        bout, bn2g, bn2b, bn2m, bn2v, x);
}

// round 16
// speedup vs baseline: 1.2562x; 1.0239x over previous
#include <cuda_runtime.h>
#include <cuda_fp16.h>
#include <math.h>
#include <stdint.h>

#define NB   8
#define C1   256
#define COUT 256
#define CM   128
#define HH   56
#define WW   56
#define HW   3136
#define NPIX (NB*HW)
#define GG   4
#define GC   32
#define EPSS 1e-5f
#define NOM  108
#define NCH2 72
#define NSTG 4
#define XPW  66
#define STG1 12288

__device__ __half g_v [NPIX*CM];
__device__ float g_om[NPIX*NOM];
__device__ __half g_xp[8*58*XPW*256];
__device__ __half g_wb[36*128*64];
__device__ __half g_hb[NPIX*CM];
__device__ __half g_tb[NPIX*CM];
__device__ __half g_ob[NPIX*CM];
__device__ __half g_wv [2*128*64];
__device__ __half g_wom[2*128*64];
__device__ __half g_wo [2*256*64];

__device__ __forceinline__ float siluf(float v){ return v / (1.f + expf(-v)); }

__device__ __forceinline__ uint32_t smem_to_u32(const void* p) {
    uint32_t a;
    asm("{ .reg .u64 t; cvta.to.shared.u64 t, %1; cvt.u32.u64 %0, t; }" : "=r"(a) : "l"(p));
    return a;
}
#define SWZ128(o) ((o) ^ (((o) >> 3) & 0x70))
#define SWZ64(o)  ((o) ^ (((o) >> 3) & 0x30))
#define CP_ASYNC16(sa, gp) \
    asm volatile("cp.async.cg.shared.global [%0], [%1], 16;" \
        :: "r"((uint32_t)(sa)), "l"(gp) : "memory")

__device__ __forceinline__ void ldsm4(uint32_t* r, uint32_t addr) {
    asm volatile("ldmatrix.sync.aligned.m8n8.x4.shared.b16 {%0,%1,%2,%3}, [%4];"
        : "=r"(r[0]), "=r"(r[1]), "=r"(r[2]), "=r"(r[3]) : "r"(addr));
}
__device__ __forceinline__ void mma16816(float* d, const uint32_t* a, uint32_t b0, uint32_t b1) {
    asm volatile("mma.sync.aligned.m16n8k16.row.col.f32.f16.f16.f32 "
        "{%0,%1,%2,%3}, {%4,%5,%6,%7}, {%8,%9}, {%0,%1,%2,%3};"
        : "+f"(d[0]), "+f"(d[1]), "+f"(d[2]), "+f"(d[3])
        : "r"(a[0]), "r"(a[1]), "r"(a[2]), "r"(a[3]), "r"(b0), "r"(b1));
}

__global__ __launch_bounds__(256) void xprep(const float* __restrict__ x)
{
    const int b = blockIdx.x, img = b / 58, yp = b % 58;
    const size_t rowbase = ((size_t)img*58 + yp) * (XPW*256);
    const int t = threadIdx.x;
    uint2 z2 = make_uint2(0u, 0u);
    for (int i = t; i < XPW*256/4; i += 256)
        ((uint2*)(g_xp + rowbase))[i] = z2;
    if (yp == 0 || yp == 57) return;
    __syncthreads();
    const int oy = yp - 1;
    __shared__ float sm[128*57];
    for (int pass = 0; pass < 2; pass++) {
        for (int i = t; i < 128*56; i += 256) {
            int c = i / 56, ox = i % 56;
            sm[c*57 + ox] = x[((size_t)(img*256 + pass*128 + c))*HW + oy*WW + ox];
        }
        __syncthreads();
        for (int i = t; i < 56*128; i += 256) {
            int ox = i >> 7, c = i & 127;
            g_xp[rowbase + (size_t)(ox+1)*256 + pass*128 + c] = __float2half(sm[c*57 + ox]);
        }
        __syncthreads();
    }
}

__global__ __launch_bounds__(256) void prep_w_all(
    const float* __restrict__ wcv1,
    const float* __restrict__ winp, const float* __restrict__ woff,
    const float* __restrict__ wmsk, const float* __restrict__ wout)
{
    int idx = blockIdx.x*256 + threadIdx.x;
    if (idx < 36*128*64) {
        int ci = idx & 63, o = (idx >> 6) & 127, ch = idx >> 13;
        int tap = ch >> 2, cc = ch & 3;
        g_wb[idx] = __float2half(wcv1[(size_t)o*2304 + (cc*64 + ci)*9 + tap]);
        return;
    }
    idx -= 36*128*64;
    if (idx >= 65536) return;
    const float* w1; const float* w2; int n1, n2, Ntot, li;
    __half* dhi;
    if (idx < 16384)      { li = idx;        w1 = winp; w2 = nullptr; n1 = 128; n2 = 0;  Ntot = 128; dhi = g_wv;  }
    else if (idx < 32768) { li = idx-16384;  w1 = woff; w2 = wmsk;    n1 = 72;  n2 = 36; Ntot = 128; dhi = g_wom; }
    else                  { li = idx-32768;  w1 = wout; w2 = nullptr; n1 = 256; n2 = 0;  Ntot = 256; dhi = g_wo;  }
    int ki = li & 63;
    int n  = (li >> 6) % Ntot;
    int kc = li / (64*Ntot);
    int k  = kc*64 + ki;
    float v = 0.f;
    if (n < n1)           v = w1[(size_t)k*n1 + n];
    else if (n < n1 + n2) v = w2[(size_t)k*n2 + (n - n1)];
    dhi[li] = __float2half(v);
}

// conv1: M=64 (1 row), N=128, K=72 chunks of 32; 4 CTAs/SM; fp16 out only
__global__ __launch_bounds__(256, 4) void conv1_mma(
    const float* __restrict__ bg, const float* __restrict__ bb,
    const float* __restrict__ bm, const float* __restrict__ bv)
{
    extern __shared__ char smraw[];
    char* smA = smraw + ((128 - (smem_to_u32(smraw) & 127)) & 127);
    const uint32_t sb = smem_to_u32(smA);
    __shared__ float s_sc[128], s_sh[128];

    const int t = threadIdx.x, wid = t >> 5, lane = t & 31;
    const int img = blockIdx.x / 56, oy = blockIdx.x % 56;

    if (t < 128) {
        float inv = rsqrtf(bv[t] + EPSS);
        float sc = bg[t]*inv;
        s_sc[t] = sc; s_sh[t] = bb[t] - bm[t]*sc;
    }

    const int c16 = t & 3;
    const int r   = t >> 2;
    const uint32_t soA = SWZ64((uint32_t)(r*64 + c16*16));
    const __half* const xrow0 = g_xp
        + ((size_t)(img*58 + oy))*(XPW*256) + c16*8 + (size_t)r*256;
    const __half* xp = xrow0;
    const __half* wp = g_wb + c16*8 + (size_t)r*64;
    int jn = 0;
    int kxr = 0, kyr = 0;
    uint32_t dstg = 0;

    auto issue = [&]() {
        uint32_t st = sb + dstg*STG1;
        CP_ASYNC16(st +        soA, xp);
        CP_ASYNC16(st + 4096 + soA, wp);
        CP_ASYNC16(st + 8192 + soA, wp + 4096);
        asm volatile("cp.async.commit_group;" ::: "memory");
        jn++;
        dstg = (dstg + 1) & 3;
        if ((jn & 7) == 0) {
            kxr++; if (kxr == 3) { kxr = 0; kyr++; }
            xp = xrow0 + (kyr*XPW + kxr)*256;
        } else {
            xp += 32;
        }
        wp += (jn & 1) ? 32 : 8160;
    };

    const int wm = wid & 1, wn = wid >> 1;
    float acc[2][4][4];
    #pragma unroll
    for (int a = 0; a < 2; a++)
        #pragma unroll
        for (int b = 0; b < 4; b++)
            #pragma unroll
            for (int c = 0; c < 4; c++) acc[a][b][c] = 0.f;

    const int lg = lane >> 3, lri = lane & 7;
    const int rsel = (lg & 1)*8 + lri;
    const int csel = (lg >> 1)*16;

    issue(); issue(); issue();
    for (int i = 0; i < NCH2; i++) {
        int rem = NCH2 - 1 - i;
        if (rem >= 2)      asm volatile("cp.async.wait_group 2;" ::: "memory");
        else if (rem == 1) asm volatile("cp.async.wait_group 1;" ::: "memory");
        else               asm volatile("cp.async.wait_group 0;" ::: "memory");
        __syncthreads();
        if (i + 3 < NCH2) issue();

        uint32_t base = sb + (i & 3)*STG1;
        #pragma unroll
        for (int ks = 0; ks < 2; ks++) {
            int cb = ks*32 + csel;
            uint32_t ah[2][4], bh[2][4];
            #pragma unroll
            for (int mf = 0; mf < 2; mf++) {
                int row = wm*32 + mf*16 + rsel;
                ldsm4(ah[mf], base + SWZ64((uint32_t)(row*64 + cb)));
            }
            #pragma unroll
            for (int nb = 0; nb < 2; nb++) {
                int row = wn*32 + nb*16 + rsel;
                ldsm4(bh[nb], base + 4096 + SWZ64((uint32_t)(row*64 + cb)));
            }
            #pragma unroll
            for (int mf = 0; mf < 2; mf++)
                #pragma unroll
                for (int nf = 0; nf < 4; nf++)
                    mma16816(acc[mf][nf], ah[mf], bh[nf>>1][nf&1], bh[nf>>1][(nf&1)+2]);
        }
    }

    const int ro = lane >> 2, co = (lane & 3) << 1;
    #pragma unroll
    for (int mf = 0; mf < 2; mf++) {
        #pragma unroll
        for (int half = 0; half < 2; half++) {
            int ox = wm*32 + mf*16 + half*8 + ro;
            if (ox < 56) {
                size_t pidbase = ((size_t)(img*HW + oy*WW + ox))*CM;
                #pragma unroll
                for (int nf = 0; nf < 4; nf++) {
                    int c = wn*32 + nf*8 + co;
                    float vx = siluf(acc[mf][nf][half*2+0]*s_sc[c]   + s_sh[c]);
                    float vy = siluf(acc[mf][nf][half*2+1]*s_sc[c+1] + s_sh[c+1]);
                    *(__half2*)(g_hb + pidbase + c) =
                        __halves2half2(__float2half(vx), __float2half(vy));
                }
            }
        }
    }
}

// EPI 2: NCHW resid epilogue; EPI 4: fused value(y=0,fp16) + offset/mask(y=1,fp32)
template<int EPI>
__global__ __launch_bounds__(256, 4) void gemm_tc(
    const __half* __restrict__ Ahi, const __half* __restrict__ Bhi,
    int Ntot, int Nout, int N1,
    const float* __restrict__ bias, const float* __restrict__ bias2,
    float* __restrict__ C,
    const float* __restrict__ eb,
    const float* __restrict__ bg, const float* __restrict__ bb,
    const float* __restrict__ bm, const float* __restrict__ bv,
    const float* __restrict__ resid,
    const __half* __restrict__ A2, const __half* __restrict__ B2,
    const float* __restrict__ bias3, float* __restrict__ Calt)
{
    extern __shared__ char smraw[];
    char* smA = smraw + ((1024 - (smem_to_u32(smraw) & 1023)) & 1023);
    const uint32_t sbA = smem_to_u32(smA);
    const uint32_t sbB = sbA + 16384;

    const int t = threadIdx.x, wid = t >> 5, lane = t & 31;
    const int m0 = blockIdx.x * 64;
    int n0 = blockIdx.y * 128;

    bool isOM = false;
    if (EPI == 4) {
        isOM = (blockIdx.y >= 1);
        n0 = 0;
        if (isOM) {
            Ahi = A2; Bhi = B2;
            Nout = NOM; N1 = 72;
            bias = bias3; C = Calt;
        }
    }

    #pragma unroll
    for (int i = 0; i < 4; i++) {
        int g = t*4 + i;
        int kc = g >> 9, m = (g >> 3) & 63, c16 = g & 7;
        const __half* src = Ahi + (size_t)(m0 + m)*128 + kc*64 + c16*8;
        CP_ASYNC16(sbA + kc*8192 + SWZ128((uint32_t)(m*128 + c16*16)), src);
    }
    #pragma unroll
    for (int i = 0; i < 8; i++) {
        int g = t*8 + i;
        int kc = g >> 10, n = (g >> 3) & 127, c16 = g & 7;
        const __half* src = Bhi + ((size_t)kc*Ntot + n0 + n)*64 + c16*8;
        CP_ASYNC16(sbB + kc*16384 + SWZ128((uint32_t)(n*128 + c16*16)), src);
    }
    asm volatile("cp.async.commit_group;" ::: "memory");
    asm volatile("cp.async.wait_group 0;" ::: "memory");
    __syncthreads();

    const int wm = wid & 1, wn = wid >> 1;
    float acc[2][4][4];
    #pragma unroll
    for (int a = 0; a < 2; a++)
        #pragma unroll
        for (int b = 0; b < 4; b++)
            #pragma unroll
            for (int c = 0; c < 4; c++) acc[a][b][c] = 0.f;

    const int lg = lane >> 3, lri = lane & 7;
    const int rsel = (lg & 1)*8 + lri;
    const int csel = (lg >> 1)*16;

    #pragma unroll
    for (int kc = 0; kc < 2; kc++) {
        uint32_t aH = sbA + kc*8192;
        uint32_t bH = sbB + kc*16384;
        #pragma unroll
        for (int ks = 0; ks < 4; ks++) {
            int cb = ks*32 + csel;
            uint32_t ah[2][4], bf[2][4];
            #pragma unroll
            for (int mf = 0; mf < 2; mf++) {
                int row = wm*32 + mf*16 + rsel;
                ldsm4(ah[mf], aH + SWZ128((uint32_t)(row*128 + cb)));
            }
            #pragma unroll
            for (int nb = 0; nb < 2; nb++) {
                int row = wn*32 + nb*16 + rsel;
                ldsm4(bf[nb], bH + SWZ128((uint32_t)(row*128 + cb)));
            }
            #pragma unroll
            for (int mf = 0; mf < 2; mf++)
                #pragma unroll
                for (int nf = 0; nf < 4; nf++)
                    mma16816(acc[mf][nf], ah[mf], bf[nf>>1][nf&1], bf[nf>>1][(nf&1)+2]);
        }
    }

    const int ro = lane >> 2, co = (lane & 3) << 1;
    if (EPI != 2) {
        const bool fp16out = (EPI == 4 && !isOM);
        #pragma unroll
        for (int mf = 0; mf < 2; mf++) {
            #pragma unroll
            for (int half = 0; half < 2; half++) {
                int m = wm*32 + mf*16 + half*8 + ro;
                size_t rowb = (size_t)(m0 + m)*Nout;
                #pragma unroll
                for (int nf = 0; nf < 4; nf++) {
                    int c = n0 + wn*32 + nf*8 + co;
                    if (c < Nout) {
                        float b0 = (c   < N1) ? bias[c]   : ((c   < Nout) ? bias2[c-N1]   : 0.f);
                        float b1 = (c+1 < N1) ? bias[c+1] : ((c+1 < Nout) ? bias2[c+1-N1] : 0.f);
                        float ox = acc[mf][nf][half*2+0] + b0;
                        float oyv = acc[mf][nf][half*2+1] + b1;
                        if (fp16out) {
                            __half* Ch = (__half*)C;
                            *(__half2*)(Ch + rowb + c) =
                                __halves2half2(__float2half(ox), __float2half(oyv));
                        } else {
                            float2 o2; o2.x = ox; o2.y = oyv;
                            *(float2*)(C + rowb + c) = o2;
                        }
                    }
                }
            }
        }
    } else {
        __syncthreads();
        float* st = (float*)smA;
        #pragma unroll
        for (int mf = 0; mf < 2; mf++) {
            #pragma unroll
            for (int half = 0; half < 2; half++) {
                int m = wm*32 + mf*16 + half*8 + ro;
                #pragma unroll
                for (int nf = 0; nf < 4; nf++) {
                    int cl = wn*32 + nf*8 + co;
                    int c  = n0 + cl;
                    float inv0 = rsqrtf(bv[c] + EPSS);
                    float sc0  = bg[c]*inv0;
                    float v0 = (acc[mf][nf][half*2+0] + eb[c])*sc0 + (bb[c] - bm[c]*sc0);
                    float inv1 = rsqrtf(bv[c+1] + EPSS);
                    float sc1  = bg[c+1]*inv1;
                    float v1 = (acc[mf][nf][half*2+1] + eb[c+1])*sc1 + (bb[c+1] - bm[c+1]*sc1);
                    st[cl*66 + m]     = siluf(v0);
                    st[(cl+1)*66 + m] = siluf(v1);
                }
            }
        }
        __syncthreads();
        const int mloc = t & 63, nsub = t >> 6;
        const int mg = m0 + mloc;
        const int img = mg / HW;
        const int pp  = mg - img*HW;
        const size_t ob = (size_t)img*COUT*HW + pp;
        #pragma unroll
        for (int i = 0; i < 32; i++) {
            int n = nsub + i*4;
            size_t adr = ob + (size_t)(n0 + n)*HW;
            C[adr] = resid[adr] + st[n*66 + mloc];
        }
    }
}

__global__ __launch_bounds__(128) void dw_ln_gelu(
    const float* __restrict__ wdw, const float* __restrict__ bdw,
    const float* __restrict__ lg,  const float* __restrict__ lb)
{
    __shared__ float s_w[9*128];
    __shared__ float s_b[128], s_g[128], s_lb[128];
    const int t = threadIdx.x;
    #pragma unroll
    for (int i = 0; i < 9; i++) s_w[i*128 + t] = wdw[t*9 + i];
    s_b[t] = bdw[t]; s_g[t] = lg[t]; s_lb[t] = lb[t];
    __syncthreads();

    const int warp = t >> 5, lane = t & 31;
    const int pix = blockIdx.x*4 + warp;
    const int img = pix / HW;
    const int p   = pix - img*HW;
    const int py  = p / WW, px = p - py*WW;
    const __half* hb = g_hb + (size_t)img*HW*CM;
    const int c0 = lane << 2;

    float sx = s_b[c0], sy = s_b[c0+1], sz = s_b[c0+2], sw = s_b[c0+3];
    #pragma unroll
    for (int ky = 0; ky < 3; ky++) {
        int yy = py + ky - 1;
        if ((unsigned)yy >= HH) continue;
        #pragma unroll
        for (int kx = 0; kx < 3; kx++) {
            int xx = px + kx - 1;
            if ((unsigned)xx >= WW) continue;
            const __half* hp = hb + (size_t)(yy*WW + xx)*CM + c0;
            float2 v01 = __half22float2(*(const __half2*)hp);
            float2 v23 = __half22float2(*(const __half2*)(hp + 2));
            const float* wk = s_w + (ky*3 + kx)*128 + c0;
            sx = fmaf(v01.x, wk[0], sx);
            sy = fmaf(v01.y, wk[1], sy);
            sz = fmaf(v23.x, wk[2], sz);
            sw = fmaf(v23.y, wk[3], sw);
        }
    }
    float r1 = sx + sy + sz + sw;
    float r2 = sx*sx + sy*sy + sz*sz + sw*sw;
    #pragma unroll
    for (int o = 16; o; o >>= 1) {
        r1 += __shfl_xor_sync(0xffffffffu, r1, o);
        r2 += __shfl_xor_sync(0xffffffffu, r2, o);
    }
    float mu  = r1 * (1.f/CM);
    float var = r2 * (1.f/CM) - mu*mu;
    float rs  = rsqrtf(var + EPSS);
    float vv[4] = {sx, sy, sz, sw};
    __half hs[4];
    #pragma unroll
    for (int j = 0; j < 4; j++) {
        float tn = (vv[j] - mu)*rs*s_g[c0+j] + s_lb[c0+j];
        float ge = 0.5f*tn*(1.f + erff(tn*0.70710678118654752f));
        hs[j] = __float2half(ge);
    }
    size_t a = (size_t)pix*CM + c0;
    *(__half2*)(g_tb + a)     = __halves2half2(hs[0], hs[1]);
    *(__half2*)(g_tb + a + 2) = __halves2half2(hs[2], hs[3]);
}

__global__ __launch_bounds__(256) void dcn_core()
{
    int gw   = (blockIdx.x*blockDim.x + threadIdx.x) >> 5;
    int lane = threadIdx.x & 31;
    if (gw >= NPIX*GG) return;
    int pid = gw >> 2;
    int g   = gw & 3;
    int img = pid / HW;
    int p   = pid - img*HW;
    int iy  = p / WW;
    int ix  = p - iy*WW;

    const float* om = g_om + (size_t)pid*NOM;
    float lgt = (lane < 9) ? om[72 + g*9 + lane] : -1e30f;
    float mx = lgt;
    #pragma unroll
    for (int o = 16; o; o >>= 1) mx = fmaxf(mx, __shfl_xor_sync(0xffffffffu, mx, o));
    float e = (lane < 9) ? expf(lgt - mx) : 0.f;
    float se = e;
    #pragma unroll
    for (int o = 16; o; o >>= 1) se += __shfl_xor_sync(0xffffffffu, se, o);
    float inv = 1.f / se;

    const __half* vb = g_v + (size_t)img*HW*CM + g*GC + lane;
    float acc = 0.f;
    #pragma unroll
    for (int k = 0; k < 9; k++) {
        float mk = __shfl_sync(0xffffffffu, e, k) * inv;
        float dx = om[(g*9 + k)*2];
        float dy = om[(g*9 + k)*2 + 1];
        int kxi = k / 3;
        int kyi = k - kxi*3;
        float fx = (float)(ix + kxi) + dx;
        float fy = (float)(iy + kyi) + dy;
        float x0f = floorf(fx), y0f = floorf(fy);
        float wx = fx - x0f, wy = fy - y0f;
        int xm = (int)x0f - 1, ym = (int)y0f - 1;
        float v00 = 0.f, v01 = 0.f, v10 = 0.f, v11 = 0.f;
        bool vx0 = (unsigned)xm     < WW;
        bool vx1 = (unsigned)(xm+1) < WW;
        bool vy0 = (unsigned)ym     < HH;
        bool vy1 = (unsigned)(ym+1) < HH;
        if (vy0 && vx0) v00 = __half2float(vb[(size_t)(ym*WW + xm      )*CM]);
        if (vy0 && vx1) v01 = __half2float(vb[(size_t)(ym*WW + xm + 1  )*CM]);
        if (vy1 && vx0) v10 = __half2float(vb[(size_t)((ym+1)*WW + xm  )*CM]);
        if (vy1 && vx1) v11 = __half2float(vb[(size_t)((ym+1)*WW + xm+1)*CM]);
        float sv = v00*(1.f-wy)*(1.f-wx) + v01*(1.f-wy)*wx
                 + v10*wy*(1.f-wx)       + v11*wy*wx;
        acc = fmaf(mk, sv, acc);
    }
    g_ob[(size_t)pid*CM + g*GC + lane] = __float2half(acc);
}

extern "C" void kernel_launch(void* const* d_in, const int* in_sizes, int n_in,
                              void* d_out, int out_size)
{
    const float* x    = (const float*)d_in[0];
    const float* wcv1 = (const float*)d_in[1];
    const float* bn1g = (const float*)d_in[2];
    const float* bn1b = (const float*)d_in[3];
    const float* bn1m = (const float*)d_in[4];
    const float* bn1v = (const float*)d_in[5];
    const float* wdw  = (const float*)d_in[6];
    const float* bdw  = (const float*)d_in[7];
    const float* lng  = (const float*)d_in[8];
    const float* lnb  = (const float*)d_in[9];
    const float* winp = (const float*)d_in[10];
    const float* binp = (const float*)d_in[11];
    const float* woff = (const float*)d_in[12];
    const float* boff = (const float*)d_in[13];
    const float* wmsk = (const float*)d_in[14];
    const float* bmsk = (const float*)d_in[15];
    const float* wout = (const float*)d_in[16];
    const float* bout = (const float*)d_in[17];
    const float* bn2g = (const float*)d_in[18];
    const float* bn2b = (const float*)d_in[19];
    const float* bn2m = (const float*)d_in[20];
    const float* bn2v = (const float*)d_in[21];
    float* out = (float*)d_out;

    float *pom;
    __half *pv;
    cudaGetSymbolAddress((void**)&pv,  g_v);
    cudaGetSymbolAddress((void**)&pom, g_om);
    __half *hb, *tb, *ob, *wv, *womp, *wo;
    cudaGetSymbolAddress((void**)&hb, g_hb);
    cudaGetSymbolAddress((void**)&tb, g_tb);
    cudaGetSymbolAddress((void**)&ob, g_ob);
    cudaGetSymbolAddress((void**)&wv, g_wv);
    cudaGetSymbolAddress((void**)&womp, g_wom);
    cudaGetSymbolAddress((void**)&wo, g_wo);

    const int smem_conv = NSTG*STG1 + 128;
    const int smem_gemm = 48*1024 + 1024;
    cudaFuncSetAttribute(conv1_mma, cudaFuncAttributeMaxDynamicSharedMemorySize, smem_conv);
    cudaFuncSetAttribute(gemm_tc<4>, cudaFuncAttributeMaxDynamicSharedMemorySize, smem_gemm);
    cudaFuncSetAttribute(gemm_tc<2>, cudaFuncAttributeMaxDynamicSharedMemorySize, smem_gemm);

    xprep<<<8*58, 256>>>(x);
    prep_w_all<<<(36*128*64 + 65536 + 255)/256, 256>>>(wcv1, winp, woff, wmsk, wout);
    conv1_mma<<<8*56, 256, smem_conv>>>(bn1g, bn1b, bn1m, bn1v);
    dw_ln_gelu<<<NPIX/4, 128>>>(wdw, bdw, lng, lnb);

    gemm_tc<4><<<dim3(NPIX/64, 2), 256, smem_gemm>>>(hb, wv,
        128, 128, 128, binp, bmsk, (float*)pv,
        nullptr, nullptr, nullptr, nullptr, nullptr, nullptr,
        tb, womp, boff, pom);
    dcn_core<<<(NPIX*GG)/8, 256>>>();
    gemm_tc<2><<<dim3(NPIX/64, 2), 256, smem_gemm>>>(ob, wo,
        256, 256, 256, nullptr, nullptr, out,
        bout, bn2g, bn2b, bn2m, bn2v, x,
        nullptr, nullptr, nullptr, nullptr);
}

// round 17
// speedup vs baseline: 1.5240x; 1.2132x over previous
#include <cuda_runtime.h>
#include <cuda_fp16.h>
#include <math.h>
#include <stdint.h>

#define NB   8
#define C1   256
#define COUT 256
#define CM   128
#define HH   56
#define WW   56
#define HW   3136
#define NPIX (NB*HW)
#define GG   4
#define GC   32
#define EPSS 1e-5f
#define NOM  108
#define NCH2 72
#define NSTG 4
#define XPW  66
#define STG1 12288

__device__ __half g_v [NPIX*CM];
__device__ float g_om[NPIX*NOM];
__device__ __half g_xp[8*58*XPW*256];
__device__ __half g_wb[36*128*64];
__device__ __half g_hb[NPIX*CM];
__device__ __half g_tb[NPIX*CM];
__device__ __half g_ob[NPIX*CM];
__device__ __half g_wv [2*128*64];
__device__ __half g_wom[2*128*64];
__device__ __half g_wo [2*256*64];

__device__ __forceinline__ float siluf(float v){ return v / (1.f + expf(-v)); }

__device__ __forceinline__ uint32_t smem_to_u32(const void* p) {
    uint32_t a;
    asm("{ .reg .u64 t; cvta.to.shared.u64 t, %1; cvt.u32.u64 %0, t; }" : "=r"(a) : "l"(p));
    return a;
}
#define SWZ128(o) ((o) ^ (((o) >> 3) & 0x70))
#define SWZ64(o)  ((o) ^ (((o) >> 3) & 0x30))
#define CP_ASYNC16(sa, gp) \
    asm volatile("cp.async.cg.shared.global [%0], [%1], 16;" \
        :: "r"((uint32_t)(sa)), "l"(gp) : "memory")

__device__ __forceinline__ void ldsm4(uint32_t* r, uint32_t addr) {
    asm volatile("ldmatrix.sync.aligned.m8n8.x4.shared.b16 {%0,%1,%2,%3}, [%4];"
        : "=r"(r[0]), "=r"(r[1]), "=r"(r[2]), "=r"(r[3]) : "r"(addr));
}
__device__ __forceinline__ void mma16816(float* d, const uint32_t* a, uint32_t b0, uint32_t b1) {
    asm volatile("mma.sync.aligned.m16n8k16.row.col.f32.f16.f16.f32 "
        "{%0,%1,%2,%3}, {%4,%5,%6,%7}, {%8,%9}, {%0,%1,%2,%3};"
        : "+f"(d[0]), "+f"(d[1]), "+f"(d[2]), "+f"(d[3])
        : "r"(a[0]), "r"(a[1]), "r"(a[2]), "r"(a[3]), "r"(b0), "r"(b1));
}

__global__ __launch_bounds__(256) void xprep(const float* __restrict__ x)
{
    const int b = blockIdx.x, img = b / 58, yp = b % 58;
    const size_t rowbase = ((size_t)img*58 + yp) * (XPW*256);
    const int t = threadIdx.x;
    uint2 z2 = make_uint2(0u, 0u);
    if (yp == 0 || yp == 57) {
        for (int i = t; i < XPW*256/4; i += 256)
            ((uint2*)(g_xp + rowbase))[i] = z2;
        return;
    }
    // interior rows: zero only col 0 and cols 57..65
    for (int j = t; j < 640; j += 256) {
        int ho = j*4;
        size_t a;
        if (ho < 256) a = rowbase + ho;
        else {
            int ho2 = ho - 256;
            a = rowbase + (size_t)(57 + (ho2 >> 8))*256 + (ho2 & 255);
        }
        *(uint2*)(g_xp + a) = z2;
    }
    __syncthreads();
    const int oy = yp - 1;
    __shared__ float sm[128*57];
    for (int pass = 0; pass < 2; pass++) {
        for (int i = t; i < 128*56; i += 256) {
            int c = i / 56, ox = i % 56;
            sm[c*57 + ox] = x[((size_t)(img*256 + pass*128 + c))*HW + oy*WW + ox];
        }
        __syncthreads();
        for (int i = t; i < 56*128; i += 256) {
            int ox = i >> 7, c = i & 127;
            g_xp[rowbase + (size_t)(ox+1)*256 + pass*128 + c] = __float2half(sm[c*57 + ox]);
        }
        __syncthreads();
    }
}

__global__ __launch_bounds__(256) void prep_w_all(
    const float* __restrict__ wcv1,
    const float* __restrict__ winp, const float* __restrict__ woff,
    const float* __restrict__ wmsk, const float* __restrict__ wout)
{
    int idx = blockIdx.x*256 + threadIdx.x;
    if (idx < 36*128*64) {
        int ci = idx & 63, o = (idx >> 6) & 127, ch = idx >> 13;
        int tap = ch >> 2, cc = ch & 3;
        g_wb[idx] = __float2half(wcv1[(size_t)o*2304 + (cc*64 + ci)*9 + tap]);
        return;
    }
    idx -= 36*128*64;
    if (idx >= 65536) return;
    const float* w1; const float* w2; int n1, n2, Ntot, li;
    __half* dhi;
    if (idx < 16384)      { li = idx;        w1 = winp; w2 = nullptr; n1 = 128; n2 = 0;  Ntot = 128; dhi = g_wv;  }
    else if (idx < 32768) { li = idx-16384;  w1 = woff; w2 = wmsk;    n1 = 72;  n2 = 36; Ntot = 128; dhi = g_wom; }
    else                  { li = idx-32768;  w1 = wout; w2 = nullptr; n1 = 256; n2 = 0;  Ntot = 256; dhi = g_wo;  }
    int ki = li & 63;
    int n  = (li >> 6) % Ntot;
    int kc = li / (64*Ntot);
    int k  = kc*64 + ki;
    float v = 0.f;
    if (n < n1)           v = w1[(size_t)k*n1 + n];
    else if (n < n1 + n2) v = w2[(size_t)k*n2 + (n - n1)];
    dhi[li] = __float2half(v);
}

// conv1: M=64 (1 row), N=128, K=72 chunks of 32; 4 CTAs/SM; fp16 out only
__global__ __launch_bounds__(256, 4) void conv1_mma(
    const float* __restrict__ bg, const float* __restrict__ bb,
    const float* __restrict__ bm, const float* __restrict__ bv)
{
    extern __shared__ char smraw[];
    char* smA = smraw + ((128 - (smem_to_u32(smraw) & 127)) & 127);
    const uint32_t sb = smem_to_u32(smA);
    __shared__ float s_sc[128], s_sh[128];

    const int t = threadIdx.x, wid = t >> 5, lane = t & 31;
    const int img = blockIdx.x / 56, oy = blockIdx.x % 56;

    if (t < 128) {
        float inv = rsqrtf(bv[t] + EPSS);
        float sc = bg[t]*inv;
        s_sc[t] = sc; s_sh[t] = bb[t] - bm[t]*sc;
    }

    const int c16 = t & 3;
    const int r   = t >> 2;
    const uint32_t soA = SWZ64((uint32_t)(r*64 + c16*16));
    const __half* const xrow0 = g_xp
        + ((size_t)(img*58 + oy))*(XPW*256) + c16*8 + (size_t)r*256;
    const __half* xp = xrow0;
    const __half* wp = g_wb + c16*8 + (size_t)r*64;
    int jn = 0;
    int kxr = 0, kyr = 0;
    uint32_t dstg = 0;

    auto issue = [&]() {
        uint32_t st = sb + dstg*STG1;
        CP_ASYNC16(st +        soA, xp);
        CP_ASYNC16(st + 4096 + soA, wp);
        CP_ASYNC16(st + 8192 + soA, wp + 4096);
        asm volatile("cp.async.commit_group;" ::: "memory");
        jn++;
        dstg = (dstg + 1) & 3;
        if ((jn & 7) == 0) {
            kxr++; if (kxr == 3) { kxr = 0; kyr++; }
            xp = xrow0 + (kyr*XPW + kxr)*256;
        } else {
            xp += 32;
        }
        wp += (jn & 1) ? 32 : 8160;
    };

    const int wm = wid & 1, wn = wid >> 1;
    float acc[2][4][4];
    #pragma unroll
    for (int a = 0; a < 2; a++)
        #pragma unroll
        for (int b = 0; b < 4; b++)
            #pragma unroll
            for (int c = 0; c < 4; c++) acc[a][b][c] = 0.f;

    const int lg = lane >> 3, lri = lane & 7;
    const int rsel = (lg & 1)*8 + lri;
    const int csel = (lg >> 1)*16;

    issue(); issue(); issue();
    for (int i = 0; i < NCH2; i++) {
        int rem = NCH2 - 1 - i;
        if (rem >= 2)      asm volatile("cp.async.wait_group 2;" ::: "memory");
        else if (rem == 1) asm volatile("cp.async.wait_group 1;" ::: "memory");
        else               asm volatile("cp.async.wait_group 0;" ::: "memory");
        __syncthreads();
        if (i + 3 < NCH2) issue();

        uint32_t base = sb + (i & 3)*STG1;
        #pragma unroll
        for (int ks = 0; ks < 2; ks++) {
            int cb = ks*32 + csel;
            uint32_t ah[2][4], bh[2][4];
            #pragma unroll
            for (int mf = 0; mf < 2; mf++) {
                int row = wm*32 + mf*16 + rsel;
                ldsm4(ah[mf], base + SWZ64((uint32_t)(row*64 + cb)));
            }
            #pragma unroll
            for (int nb = 0; nb < 2; nb++) {
                int row = wn*32 + nb*16 + rsel;
                ldsm4(bh[nb], base + 4096 + SWZ64((uint32_t)(row*64 + cb)));
            }
            #pragma unroll
            for (int mf = 0; mf < 2; mf++)
                #pragma unroll
                for (int nf = 0; nf < 4; nf++)
                    mma16816(acc[mf][nf], ah[mf], bh[nf>>1][nf&1], bh[nf>>1][(nf&1)+2]);
        }
    }

    const int ro = lane >> 2, co = (lane & 3) << 1;
    #pragma unroll
    for (int mf = 0; mf < 2; mf++) {
        #pragma unroll
        for (int half = 0; half < 2; half++) {
            int ox = wm*32 + mf*16 + half*8 + ro;
            if (ox < 56) {
                size_t pidbase = ((size_t)(img*HW + oy*WW + ox))*CM;
                #pragma unroll
                for (int nf = 0; nf < 4; nf++) {
                    int c = wn*32 + nf*8 + co;
                    float vx = siluf(acc[mf][nf][half*2+0]*s_sc[c]   + s_sh[c]);
                    float vy = siluf(acc[mf][nf][half*2+1]*s_sc[c+1] + s_sh[c+1]);
                    *(__half2*)(g_hb + pidbase + c) =
                        __halves2half2(__float2half(vx), __float2half(vy));
                }
            }
        }
    }
}

// EPI 2: NCHW resid epilogue; EPI 4: fused value(y=0,fp16) + offset/mask(y=1,fp32)
template<int EPI>
__global__ __launch_bounds__(256, 4) void gemm_tc(
    const __half* __restrict__ Ahi, const __half* __restrict__ Bhi,
    int Ntot, int Nout, int N1,
    const float* __restrict__ bias, const float* __restrict__ bias2,
    float* __restrict__ C,
    const float* __restrict__ eb,
    const float* __restrict__ bg, const float* __restrict__ bb,
    const float* __restrict__ bm, const float* __restrict__ bv,
    const float* __restrict__ resid,
    const __half* __restrict__ A2, const __half* __restrict__ B2,
    const float* __restrict__ bias3, float* __restrict__ Calt)
{
    extern __shared__ char smraw[];
    char* smA = smraw + ((1024 - (smem_to_u32(smraw) & 1023)) & 1023);
    const uint32_t sbA = smem_to_u32(smA);
    const uint32_t sbB = sbA + 16384;

    const int t = threadIdx.x, wid = t >> 5, lane = t & 31;
    const int m0 = blockIdx.x * 64;
    int n0 = blockIdx.y * 128;

    bool isOM = false;
    if (EPI == 4) {
        isOM = (blockIdx.y >= 1);
        n0 = 0;
        if (isOM) {
            Ahi = A2; Bhi = B2;
            Nout = NOM; N1 = 72;
            bias = bias3; C = Calt;
        }
    }

    #pragma unroll
    for (int i = 0; i < 4; i++) {
        int g = t*4 + i;
        int kc = g >> 9, m = (g >> 3) & 63, c16 = g & 7;
        const __half* src = Ahi + (size_t)(m0 + m)*128 + kc*64 + c16*8;
        CP_ASYNC16(sbA + kc*8192 + SWZ128((uint32_t)(m*128 + c16*16)), src);
    }
    #pragma unroll
    for (int i = 0; i < 8; i++) {
        int g = t*8 + i;
        int kc = g >> 10, n = (g >> 3) & 127, c16 = g & 7;
        const __half* src = Bhi + ((size_t)kc*Ntot + n0 + n)*64 + c16*8;
        CP_ASYNC16(sbB + kc*16384 + SWZ128((uint32_t)(n*128 + c16*16)), src);
    }
    asm volatile("cp.async.commit_group;" ::: "memory");
    asm volatile("cp.async.wait_group 0;" ::: "memory");
    __syncthreads();

    const int wm = wid & 1, wn = wid >> 1;
    float acc[2][4][4];
    #pragma unroll
    for (int a = 0; a < 2; a++)
        #pragma unroll
        for (int b = 0; b < 4; b++)
            #pragma unroll
            for (int c = 0; c < 4; c++) acc[a][b][c] = 0.f;

    const int lg = lane >> 3, lri = lane & 7;
    const int rsel = (lg & 1)*8 + lri;
    const int csel = (lg >> 1)*16;

    #pragma unroll
    for (int kc = 0; kc < 2; kc++) {
        uint32_t aH = sbA + kc*8192;
        uint32_t bH = sbB + kc*16384;
        #pragma unroll
        for (int ks = 0; ks < 4; ks++) {
            int cb = ks*32 + csel;
            uint32_t ah[2][4], bf[2][4];
            #pragma unroll
            for (int mf = 0; mf < 2; mf++) {
                int row = wm*32 + mf*16 + rsel;
                ldsm4(ah[mf], aH + SWZ128((uint32_t)(row*128 + cb)));
            }
            #pragma unroll
            for (int nb = 0; nb < 2; nb++) {
                int row = wn*32 + nb*16 + rsel;
                ldsm4(bf[nb], bH + SWZ128((uint32_t)(row*128 + cb)));
            }
            #pragma unroll
            for (int mf = 0; mf < 2; mf++)
                #pragma unroll
                for (int nf = 0; nf < 4; nf++)
                    mma16816(acc[mf][nf], ah[mf], bf[nf>>1][nf&1], bf[nf>>1][(nf&1)+2]);
        }
    }

    const int ro = lane >> 2, co = (lane & 3) << 1;
    if (EPI != 2) {
        const bool fp16out = (EPI == 4 && !isOM);
        #pragma unroll
        for (int mf = 0; mf < 2; mf++) {
            #pragma unroll
            for (int half = 0; half < 2; half++) {
                int m = wm*32 + mf*16 + half*8 + ro;
                size_t rowb = (size_t)(m0 + m)*Nout;
                #pragma unroll
                for (int nf = 0; nf < 4; nf++) {
                    int c = n0 + wn*32 + nf*8 + co;
                    if (c < Nout) {
                        float b0 = (c   < N1) ? bias[c]   : ((c   < Nout) ? bias2[c-N1]   : 0.f);
                        float b1 = (c+1 < N1) ? bias[c+1] : ((c+1 < Nout) ? bias2[c+1-N1] : 0.f);
                        float ox = acc[mf][nf][half*2+0] + b0;
                        float oyv = acc[mf][nf][half*2+1] + b1;
                        if (fp16out) {
                            __half* Ch = (__half*)C;
                            *(__half2*)(Ch + rowb + c) =
                                __halves2half2(__float2half(ox), __float2half(oyv));
                        } else {
                            float2 o2; o2.x = ox; o2.y = oyv;
                            *(float2*)(C + rowb + c) = o2;
                        }
                    }
                }
            }
        }
    } else {
        __syncthreads();
        float* st = (float*)smA;
        #pragma unroll
        for (int mf = 0; mf < 2; mf++) {
            #pragma unroll
            for (int half = 0; half < 2; half++) {
                int m = wm*32 + mf*16 + half*8 + ro;
                #pragma unroll
                for (int nf = 0; nf < 4; nf++) {
                    int cl = wn*32 + nf*8 + co;
                    int c  = n0 + cl;
                    float inv0 = rsqrtf(bv[c] + EPSS);
                    float sc0  = bg[c]*inv0;
                    float v0 = (acc[mf][nf][half*2+0] + eb[c])*sc0 + (bb[c] - bm[c]*sc0);
                    float inv1 = rsqrtf(bv[c+1] + EPSS);
                    float sc1  = bg[c+1]*inv1;
                    float v1 = (acc[mf][nf][half*2+1] + eb[c+1])*sc1 + (bb[c+1] - bm[c+1]*sc1);
                    st[cl*66 + m]     = siluf(v0);
                    st[(cl+1)*66 + m] = siluf(v1);
                }
            }
        }
        __syncthreads();
        const int mloc = t & 63, nsub = t >> 6;
        const int mg = m0 + mloc;
        const int img = mg / HW;
        const int pp  = mg - img*HW;
        const size_t ob = (size_t)img*COUT*HW + pp;
        #pragma unroll
        for (int i = 0; i < 32; i++) {
            int n = nsub + i*4;
            size_t adr = ob + (size_t)(n0 + n)*HW;
            C[adr] = resid[adr] + st[n*66 + mloc];
        }
    }
}

__global__ __launch_bounds__(128) void dw_ln_gelu(
    const float* __restrict__ wdw, const float* __restrict__ bdw,
    const float* __restrict__ lg,  const float* __restrict__ lb)
{
    __shared__ float s_w[9*128];
    __shared__ float s_b[128], s_g[128], s_lb[128];
    const int t = threadIdx.x;
    #pragma unroll
    for (int i = 0; i < 9; i++) s_w[i*128 + t] = wdw[t*9 + i];
    s_b[t] = bdw[t]; s_g[t] = lg[t]; s_lb[t] = lb[t];
    __syncthreads();

    const int warp = t >> 5, lane = t & 31;
    const int pix = blockIdx.x*4 + warp;
    const int img = pix / HW;
    const int p   = pix - img*HW;
    const int py  = p / WW, px = p - py*WW;
    const __half* hb = g_hb + (size_t)img*HW*CM;
    const int c0 = lane << 2;

    float sx = s_b[c0], sy = s_b[c0+1], sz = s_b[c0+2], sw = s_b[c0+3];
    #pragma unroll
    for (int ky = 0; ky < 3; ky++) {
        int yy = py + ky - 1;
        if ((unsigned)yy >= HH) continue;
        #pragma unroll
        for (int kx = 0; kx < 3; kx++) {
            int xx = px + kx - 1;
            if ((unsigned)xx >= WW) continue;
            const __half* hp = hb + (size_t)(yy*WW + xx)*CM + c0;
            float2 v01 = __half22float2(*(const __half2*)hp);
            float2 v23 = __half22float2(*(const __half2*)(hp + 2));
            const float* wk = s_w + (ky*3 + kx)*128 + c0;
            sx = fmaf(v01.x, wk[0], sx);
            sy = fmaf(v01.y, wk[1], sy);
            sz = fmaf(v23.x, wk[2], sz);
            sw = fmaf(v23.y, wk[3], sw);
        }
    }
    float r1 = sx + sy + sz + sw;
    float r2 = sx*sx + sy*sy + sz*sz + sw*sw;
    #pragma unroll
    for (int o = 16; o; o >>= 1) {
        r1 += __shfl_xor_sync(0xffffffffu, r1, o);
        r2 += __shfl_xor_sync(0xffffffffu, r2, o);
    }
    float mu  = r1 * (1.f/CM);
    float var = r2 * (1.f/CM) - mu*mu;
    float rs  = rsqrtf(var + EPSS);
    float vv[4] = {sx, sy, sz, sw};
    __half hs[4];
    #pragma unroll
    for (int j = 0; j < 4; j++) {
        float tn = (vv[j] - mu)*rs*s_g[c0+j] + s_lb[c0+j];
        float ge = 0.5f*tn*(1.f + erff(tn*0.70710678118654752f));
        hs[j] = __float2half(ge);
    }
    size_t a = (size_t)pix*CM + c0;
    *(__half2*)(g_tb + a)     = __halves2half2(hs[0], hs[1]);
    *(__half2*)(g_tb + a + 2) = __halves2half2(hs[2], hs[3]);
}

// DCNv3 sampler: warp per pixel; lane = 4 channels (half2 x2), group = lane>>3
__global__ __launch_bounds__(256) void dcn_core()
{
    int pid  = (blockIdx.x*blockDim.x + threadIdx.x) >> 5;
    int lane = threadIdx.x & 31;
    if (pid >= NPIX) return;
    int img = pid / HW;
    int p   = pid - img*HW;
    int iy  = p / WW;
    int ix  = p - iy*WW;
    int g   = lane >> 3;

    const float* om = g_om + (size_t)pid*NOM;
    float l[9];
    #pragma unroll
    for (int k = 0; k < 9; k++) l[k] = om[72 + g*9 + k];
    float mx = l[0];
    #pragma unroll
    for (int k = 1; k < 9; k++) mx = fmaxf(mx, l[k]);
    float e[9]; float se = 0.f;
    #pragma unroll
    for (int k = 0; k < 9; k++) { e[k] = expf(l[k] - mx); se += e[k]; }
    float inv = 1.f / se;

    const __half* vb = g_v + (size_t)img*HW*CM + g*GC + (lane & 7)*4;
    float a0 = 0.f, a1 = 0.f, a2 = 0.f, a3 = 0.f;
    #pragma unroll
    for (int k = 0; k < 9; k++) {
        float mk = e[k]*inv;
        float dx = om[(g*9 + k)*2];
        float dy = om[(g*9 + k)*2 + 1];
        int kxi = k / 3;
        int kyi = k - kxi*3;
        float fx = (float)(ix + kxi) + dx;
        float fy = (float)(iy + kyi) + dy;
        float x0f = floorf(fx), y0f = floorf(fy);
        float wx = fx - x0f, wy = fy - y0f;
        int xm = (int)x0f - 1, ym = (int)y0f - 1;
        bool vx0 = (unsigned)xm     < WW;
        bool vx1 = (unsigned)(xm+1) < WW;
        bool vy0 = (unsigned)ym     < HH;
        bool vy1 = (unsigned)(ym+1) < HH;
        float2 c00 = make_float2(0.f,0.f), c01 = c00, c10 = c00, c11 = c00;
        float2 d00 = c00, d01 = c00, d10 = c00, d11 = c00;
        if (vy0 && vx0) {
            const __half* q = vb + (size_t)(ym*WW + xm)*CM;
            c00 = __half22float2(*(const __half2*)q);
            d00 = __half22float2(*(const __half2*)(q + 2));
        }
        if (vy0 && vx1) {
            const __half* q = vb + (size_t)(ym*WW + xm + 1)*CM;
            c01 = __half22float2(*(const __half2*)q);
            d01 = __half22float2(*(const __half2*)(q + 2));
        }
        if (vy1 && vx0) {
            const __half* q = vb + (size_t)((ym+1)*WW + xm)*CM;
            c10 = __half22float2(*(const __half2*)q);
            d10 = __half22float2(*(const __half2*)(q + 2));
        }
        if (vy1 && vx1) {
            const __half* q = vb + (size_t)((ym+1)*WW + xm + 1)*CM;
            c11 = __half22float2(*(const __half2*)q);
            d11 = __half22float2(*(const __half2*)(q + 2));
        }
        float w00 = (1.f-wy)*(1.f-wx), w01 = (1.f-wy)*wx;
        float w10 = wy*(1.f-wx),       w11 = wy*wx;
        a0 = fmaf(mk, c00.x*w00 + c01.x*w01 + c10.x*w10 + c11.x*w11, a0);
        a1 = fmaf(mk, c00.y*w00 + c01.y*w01 + c10.y*w10 + c11.y*w11, a1);
        a2 = fmaf(mk, d00.x*w00 + d01.x*w01 + d10.x*w10 + d11.x*w11, a2);
        a3 = fmaf(mk, d00.y*w00 + d01.y*w01 + d10.y*w10 + d11.y*w11, a3);
    }
    size_t oidx = (size_t)pid*CM + g*GC + (lane & 7)*4;
    *(__half2*)(g_ob + oidx)     = __halves2half2(__float2half(a0), __float2half(a1));
    *(__half2*)(g_ob + oidx + 2) = __halves2half2(__float2half(a2), __float2half(a3));
}

extern "C" void kernel_launch(void* const* d_in, const int* in_sizes, int n_in,
                              void* d_out, int out_size)
{
    const float* x    = (const float*)d_in[0];
    const float* wcv1 = (const float*)d_in[1];
    const float* bn1g = (const float*)d_in[2];
    const float* bn1b = (const float*)d_in[3];
    const float* bn1m = (const float*)d_in[4];
    const float* bn1v = (const float*)d_in[5];
    const float* wdw  = (const float*)d_in[6];
    const float* bdw  = (const float*)d_in[7];
    const float* lng  = (const float*)d_in[8];
    const float* lnb  = (const float*)d_in[9];
    const float* winp = (const float*)d_in[10];
    const float* binp = (const float*)d_in[11];
    const float* woff = (const float*)d_in[12];
    const float* boff = (const float*)d_in[13];
    const float* wmsk = (const float*)d_in[14];
    const float* bmsk = (const float*)d_in[15];
    const float* wout = (const float*)d_in[16];
    const float* bout = (const float*)d_in[17];
    const float* bn2g = (const float*)d_in[18];
    const float* bn2b = (const float*)d_in[19];
    const float* bn2m = (const float*)d_in[20];
    const float* bn2v = (const float*)d_in[21];
    float* out = (float*)d_out;

    float *pom;
    __half *pv;
    cudaGetSymbolAddress((void**)&pv,  g_v);
    cudaGetSymbolAddress((void**)&pom, g_om);
    __half *hb, *tb, *ob, *wv, *womp, *wo;
    cudaGetSymbolAddress((void**)&hb, g_hb);
    cudaGetSymbolAddress((void**)&tb, g_tb);
    cudaGetSymbolAddress((void**)&ob, g_ob);
    cudaGetSymbolAddress((void**)&wv, g_wv);
    cudaGetSymbolAddress((void**)&womp, g_wom);
    cudaGetSymbolAddress((void**)&wo, g_wo);

    const int smem_conv = NSTG*STG1 + 128;
    const int smem_gemm = 48*1024 + 1024;
    cudaFuncSetAttribute(conv1_mma, cudaFuncAttributeMaxDynamicSharedMemorySize, smem_conv);
    cudaFuncSetAttribute(gemm_tc<4>, cudaFuncAttributeMaxDynamicSharedMemorySize, smem_gemm);
    cudaFuncSetAttribute(gemm_tc<2>, cudaFuncAttributeMaxDynamicSharedMemorySize, smem_gemm);

    xprep<<<8*58, 256>>>(x);
    prep_w_all<<<(36*128*64 + 65536 + 255)/256, 256>>>(wcv1, winp, woff, wmsk, wout);
    conv1_mma<<<8*56, 256, smem_conv>>>(bn1g, bn1b, bn1m, bn1v);
    dw_ln_gelu<<<NPIX/4, 128>>>(wdw, bdw, lng, lnb);

    gemm_tc<4><<<dim3(NPIX/64, 2), 256, smem_gemm>>>(hb, wv,
        128, 128, 128, binp, bmsk, (float*)pv,
        nullptr, nullptr, nullptr, nullptr, nullptr, nullptr,
        tb, womp, boff, pom);
    dcn_core<<<NPIX/8, 256>>>();
    gemm_tc<2><<<dim3(NPIX/64, 2), 256, smem_gemm>>>(ob, wo,
        256, 256, 256, nullptr, nullptr, out,
        bout, bn2g, bn2b, bn2m, bn2v, x,
        nullptr, nullptr, nullptr, nullptr);
}